// round 13
// baseline (speedup 1.0000x reference)
#include <cuda_runtime.h>
#include <cuda_fp16.h>
#include <cstdint>
#include <cfloat>

#define NHEAD 12
#define NB    4
#define SEQ   2048
#define HDIM  64
#define CDIM  768
#define CDIM3 2304
#define MROWS (NB*SEQ)   // 8192

// fp16 scratch (static device globals: no runtime allocation)
__device__ __align__(16) __half g_q[NB*NHEAD*SEQ*HDIM];  // q pre-scaled by 0.125
__device__ __align__(16) __half g_k[NB*NHEAD*SEQ*HDIM];
__device__ __align__(16) __half g_v[NB*NHEAD*SEQ*HDIM];
__device__ __align__(16) __half g_y[MROWS*CDIM];
__device__ __align__(16) __half g_xh[MROWS*CDIM];        // x fp16
__device__ __align__(16) __half g_wah[CDIM3*CDIM];       // W_attn^T fp16 [n][k]
__device__ __align__(16) __half g_wph[CDIM*CDIM];        // W_proj^T fp16 [n][k]

__device__ __forceinline__ uint32_t h2pack(float lo, float hi) {
    uint32_t u;
    asm("cvt.rn.f16x2.f32 %0, %1, %2;" : "=r"(u) : "f"(hi), "f"(lo));
    return u;
}

__device__ __forceinline__ uint32_t smem_u32(const void* p) {
    uint32_t a;
    asm("{ .reg .u64 t; cvta.to.shared.u64 t, %1; cvt.u32.u64 %0, t; }"
        : "=r"(a) : "l"(p));
    return a;
}

#define CP16(dst, src) \
    asm volatile("cp.async.cg.shared.global [%0], [%1], 16;" \
                 :: "r"((uint32_t)(dst)), "l"((size_t)(src)) : "memory")
#define CP16A(dst, src) \
    asm volatile("cp.async.ca.shared.global [%0], [%1], 16;" \
                 :: "r"((uint32_t)(dst)), "l"((size_t)(src)) : "memory")
#define CP_COMMIT() asm volatile("cp.async.commit_group;" ::: "memory")
#define CP_WAIT0()  asm volatile("cp.async.wait_group 0;" ::: "memory")

__device__ __forceinline__ void mma16(float* d,
    uint32_t a0, uint32_t a1, uint32_t a2, uint32_t a3,
    uint32_t b0, uint32_t b1) {
    asm volatile(
      "mma.sync.aligned.m16n8k16.row.col.f32.f16.f16.f32 "
      "{%0,%1,%2,%3}, {%4,%5,%6,%7}, {%8,%9}, {%0,%1,%2,%3};\n"
      : "+f"(d[0]), "+f"(d[1]), "+f"(d[2]), "+f"(d[3])
      : "r"(a0), "r"(a1), "r"(a2), "r"(a3), "r"(b0), "r"(b1));
}

#define LDSM_X4(r0,r1,r2,r3,addr) \
    asm volatile("ldmatrix.sync.aligned.m8n8.x4.shared.b16 {%0,%1,%2,%3}, [%4];" \
        : "=r"(r0), "=r"(r1), "=r"(r2), "=r"(r3) : "r"(addr))
#define LDSM_X4T(r0,r1,r2,r3,addr) \
    asm volatile("ldmatrix.sync.aligned.m8n8.x4.trans.shared.b16 {%0,%1,%2,%3}, [%4];" \
        : "=r"(r0), "=r"(r1), "=r"(r2), "=r"(r3) : "r"(addr))

// ===================== merged prep kernel ===================================
#define XB  (MROWS*CDIM/1024)            // 6144
#define WAB ((CDIM3/32)*(CDIM/32))       // 1728
#define WPB ((CDIM/32)*(CDIM/32))        // 576

__global__ __launch_bounds__(256) void prep_all(
    const float* __restrict__ x,
    const float* __restrict__ W_attn,
    const float* __restrict__ W_proj) {
    __shared__ float t[32][33];
    int bx = blockIdx.x;
    if (bx < XB) {
        size_t i = ((size_t)bx * 256 + threadIdx.x) * 4;
        float4 v = *(const float4*)(x + i);
        uint2 o;
        o.x = h2pack(v.x, v.y);
        o.y = h2pack(v.z, v.w);
        *(uint2*)(g_xh + i) = o;
        return;
    }
    const float* src; __half* dst; int K, N, b;
    if (bx < XB + WAB) {
        b = bx - XB; src = W_attn; dst = g_wah; K = CDIM; N = CDIM3;
    } else {
        b = bx - XB - WAB; src = W_proj; dst = g_wph; K = CDIM; N = CDIM;
    }
    int nb = (b % (N/32)) * 32, kb = (b / (N/32)) * 32;
    int tx = threadIdx.x & 31, ty = threadIdx.x >> 5;
    #pragma unroll
    for (int r = 0; r < 4; r++)
        t[ty + r*8][tx] = src[(size_t)(kb + ty + r*8) * N + nb + tx];
    __syncthreads();
    #pragma unroll
    for (int r = 0; r < 4; r++)
        dst[(size_t)(nb + ty + r*8) * K + kb + tx] = __float2half_rn(t[tx][ty + r*8]);
}

// ===================== fp16 GEMM core (128x128x64, cp.async 2-stage) ========
#define GP 36                 // smem pitch in words (64 halves + 4 pad words)
#define ABS (128*GP)          // words per tile array
#define G_SMEM (2*2*ABS*4)    // 73728 B

#define GEMM_LANE_SETUP() \
    const int tid = threadIdx.x; \
    const int wid = tid >> 5, lane = tid & 31; \
    const int g = lane >> 2, tg = lane & 3; \
    const int wM = wid & 3, wN = wid >> 2; \
    const int aRow = (lane & 7) + ((lane >> 3) & 1) * 8, aWof = (lane >> 4) * 4; \
    const int bRow = (lane & 7) + ((lane >> 4) & 1) * 8, bWof = ((lane >> 3) & 1) * 4; \
    const int lrow = tid >> 3, lseg = tid & 7;

#define GEMM_ISSUE(kb, st) do { \
    size_t ko_ = (size_t)(kb)*64*2; \
    uint32_t ad_ = sb + ((st)*2*ABS)*4; \
    uint32_t bd_ = sb + ((st)*2*ABS + ABS)*4; \
    _Pragma("unroll") \
    for (int j_ = 0; j_ < 4; j_++) { \
        CP16A(ad_ + (((lrow + j_*32)*GP + lseg*4))*4, aG + (size_t)(j_*32)*CDIM*2 + ko_); \
        CP16A(bd_ + (((lrow + j_*32)*GP + lseg*4))*4, bG + (size_t)(j_*32)*CDIM*2 + ko_); \
    } \
    CP_COMMIT(); \
} while (0)

#define GEMM_MAINLOOP() \
    float acc[2][8][4]; \
    _Pragma("unroll") \
    for (int i = 0; i < 2; i++) \
        _Pragma("unroll") \
        for (int j = 0; j < 8; j++) \
            _Pragma("unroll") \
            for (int e = 0; e < 4; e++) acc[i][j][e] = 0.f; \
    GEMM_ISSUE(0, 0); \
    for (int kb = 0; kb < CDIM/64; kb++) { \
        CP_WAIT0(); \
        __syncthreads(); \
        if (kb + 1 < CDIM/64) GEMM_ISSUE(kb + 1, (kb + 1) & 1); \
        const uint32_t sbA = sb + ((kb & 1)*2*ABS)*4; \
        const uint32_t sbB = sbA + ABS*4; \
        _Pragma("unroll") \
        for (int kk = 0; kk < 4; kk++) { \
            uint32_t a0[4], a1[4]; \
            LDSM_X4(a0[0],a0[1],a0[2],a0[3], sbA + ((wM*32      + aRow)*GP + kk*8 + aWof)*4); \
            LDSM_X4(a1[0],a1[1],a1[2],a1[3], sbA + ((wM*32 + 16 + aRow)*GP + kk*8 + aWof)*4); \
            _Pragma("unroll") \
            for (int ntp = 0; ntp < 4; ntp++) { \
                uint32_t b0, b1, b2, b3; \
                LDSM_X4(b0, b1, b2, b3, \
                        sbB + ((wN*64 + ntp*16 + bRow)*GP + kk*8 + bWof)*4); \
                mma16(acc[0][2*ntp  ], a0[0],a0[1],a0[2],a0[3], b0, b1); \
                mma16(acc[0][2*ntp+1], a0[0],a0[1],a0[2],a0[3], b2, b3); \
                mma16(acc[1][2*ntp  ], a1[0],a1[1],a1[2],a1[3], b0, b1); \
                mma16(acc[1][2*ntp+1], a1[0],a1[1],a1[2],a1[3], b2, b3); \
            } \
        } \
        __syncthreads(); \
    }

// ---------------------------------------------------------------------------
// Kernel 1: qkv = xh @ wah^T + b_attn -> fp16 head-major q/k/v (q * 0.125)
// ---------------------------------------------------------------------------
__global__ __launch_bounds__(256) void qkv_gemm(const float* __restrict__ bias) {
    extern __shared__ uint32_t smw[];
    uint32_t sb = smem_u32(smw);
    GEMM_LANE_SETUP();
    const int rowBase = blockIdx.y * 128;
    const int colBase = blockIdx.x * 128;
    const size_t aG = __cvta_generic_to_global(g_xh  + (size_t)(rowBase + lrow)*CDIM + lseg*8);
    const size_t bG = __cvta_generic_to_global(g_wah + (size_t)(colBase + lrow)*CDIM + lseg*8);

    GEMM_MAINLOOP();

    const int which = colBase / CDIM;
    const int cjBase = colBase % CDIM;
    __half* dst = (which == 0) ? g_q : (which == 1 ? g_k : g_v);
    const float qs = (which == 0) ? 0.125f : 1.0f;

    #pragma unroll
    for (int mt = 0; mt < 2; mt++) {
        int r0g = rowBase + wM*32 + mt*16 + g;
        int r1g = r0g + 8;
        int b0i = r0g >> 11, t0 = r0g & 2047;
        int b1i = r1g >> 11, t1 = r1g & 2047;
        #pragma unroll
        for (int nt = 0; nt < 8; nt++) {
            int cj = cjBase + wN*64 + nt*8 + tg*2;
            int h = cj >> 6, d = cj & 63;
            int n = colBase + wN*64 + nt*8 + tg*2;
            float bb0 = bias[n], bb1 = bias[n+1];
            size_t o0 = ((size_t)(b0i*NHEAD + h)*SEQ + t0)*HDIM + d;
            size_t o1 = ((size_t)(b1i*NHEAD + h)*SEQ + t1)*HDIM + d;
            *(uint32_t*)(dst + o0) =
                h2pack((acc[mt][nt][0] + bb0)*qs, (acc[mt][nt][1] + bb1)*qs);
            *(uint32_t*)(dst + o1) =
                h2pack((acc[mt][nt][2] + bb0)*qs, (acc[mt][nt][3] + bb1)*qs);
        }
    }
}

// ---------------------------------------------------------------------------
// Kernel 3: out = y(fp16) @ wph^T + b_proj, fp32 out
// ---------------------------------------------------------------------------
__global__ __launch_bounds__(256) void proj_gemm(const float* __restrict__ bias,
                                                 float* __restrict__ out) {
    extern __shared__ uint32_t smw[];
    uint32_t sb = smem_u32(smw);
    GEMM_LANE_SETUP();
    const int rowBase = blockIdx.y * 128;
    const int colBase = blockIdx.x * 128;
    const size_t aG = __cvta_generic_to_global(g_y   + (size_t)(rowBase + lrow)*CDIM + lseg*8);
    const size_t bG = __cvta_generic_to_global(g_wph + (size_t)(colBase + lrow)*CDIM + lseg*8);

    GEMM_MAINLOOP();

    #pragma unroll
    for (int mt = 0; mt < 2; mt++) {
        int r0g = rowBase + wM*32 + mt*16 + g;
        int r1g = r0g + 8;
        #pragma unroll
        for (int nt = 0; nt < 8; nt++) {
            int n = colBase + wN*64 + nt*8 + tg*2;
            float bb0 = bias[n], bb1 = bias[n+1];
            float2 u0 = {acc[mt][nt][0] + bb0, acc[mt][nt][1] + bb1};
            float2 u1 = {acc[mt][nt][2] + bb0, acc[mt][nt][3] + bb1};
            *(float2*)(out + (size_t)r0g*CDIM + n) = u0;
            *(float2*)(out + (size_t)r1g*CDIM + n) = u1;
        }
    }
}

// ---------------------------------------------------------------------------
// Kernel 2: fp16 flash attention, Br=64 / 4 warps / 4 CTAs per SM.
// Per-warp inner code identical to the R12 version (16 rows x 64 cols,
// f16x2 ex2 softmax, K/V row permutation -> LDG.128 mask loads); only the
// CTA shape and loader maps change. 4 independent CTAs per SM double the
// latency hiding across the softmax serial chain; 128-thread barriers.
// ---------------------------------------------------------------------------
#define FB 64                          // q rows per CTA
#define KVW 36
#define KV_STAGE (64*KVW)
#define VS_BASE  (2*KV_STAGE)
#define FLASH_SMEM ((4*KV_STAGE)*4)    // 36864 B

__global__ __launch_bounds__(128, 4) void flash_attn(const float* __restrict__ mask) {
    extern __shared__ uint32_t sm[];
    uint32_t sb = smem_u32(sm);

    const int tid = threadIdx.x;
    const int wid = tid >> 5, lane = tid & 31;
    const int g = lane >> 2, tg = lane & 3;
    const int qt = (int)(gridDim.x - 1 - blockIdx.x);   // heavy tiles first
    const int h = blockIdx.y >> 2, b = blockIdx.y & 3;
    const int rw = wid * 16;

    const __half* Qg  = g_q + ((size_t)((b*NHEAD + h)*SEQ) + qt*FB)*HDIM;
    const __half* Kg0 = g_k + (size_t)((b*NHEAD + h)*SEQ)*HDIM;
    const __half* Vg0 = g_v + (size_t)((b*NHEAD + h)*SEQ)*HDIM;
    const float*  Mb  = mask + ((size_t)h*SEQ + qt*FB)*SEQ;

    // cp.async: 64 rows x 128B; 2 thr/row, 4 x 16B chunks each.
    // physical smem row = crow; global source row = perm(crow)
    const int crow = tid >> 1, cc0 = tid & 1;
    const int p15 = crow & 15;
    const int l15 = (p15 < 8) ? ((p15 >> 1)*4 + (p15 & 1))
                              : (((p15 - 8) >> 1)*4 + 2 + (p15 & 1));
    const int lsrc = (crow & ~15) | l15;
    const size_t ksrc0 = __cvta_generic_to_global(Kg0 + (size_t)lsrc*HDIM);
    const size_t vsrc0 = __cvta_generic_to_global(Vg0 + (size_t)lsrc*HDIM);
    const uint32_t kdst0 = sb + crow*KVW*4;
    const uint32_t vdst0 = sb + (VS_BASE + crow*KVW)*4;

    #define KV_ISSUE(kt, st) do { \
        size_t ks_ = ksrc0 + (size_t)(kt)*64*HDIM*2; \
        size_t vs_ = vsrc0 + (size_t)(kt)*64*HDIM*2; \
        uint32_t kd_ = kdst0 + (st)*KV_STAGE*4; \
        uint32_t vd_ = vdst0 + (st)*KV_STAGE*4; \
        _Pragma("unroll") \
        for (int j_ = 0; j_ < 4; j_++) { \
            CP16(kd_ + (cc0 + 2*j_)*16, ks_ + (cc0 + 2*j_)*16); \
            CP16(vd_ + (cc0 + 2*j_)*16, vs_ + (cc0 + 2*j_)*16); \
        } \
        CP_COMMIT(); \
    } while (0)

    KV_ISSUE(0, 0);

    uint32_t qa[4][4];
    {
        const uint32_t* q0 = (const uint32_t*)(Qg + (size_t)(rw+g)*HDIM);
        const uint32_t* q1 = (const uint32_t*)(Qg + (size_t)(rw+8+g)*HDIM);
        #pragma unroll
        for (int kk = 0; kk < 4; kk++) {
            qa[kk][0] = q0[kk*8 + tg];
            qa[kk][1] = q1[kk*8 + tg];
            qa[kk][2] = q0[kk*8 + tg + 4];
            qa[kk][3] = q1[kk*8 + tg + 4];
        }
    }

    const int kRow = (lane & 7) + ((lane >> 4) & 1) * 8;
    const int kWof = ((lane >> 3) & 1) * 4;
    const int vRow = (lane & 7) + ((lane >> 3) & 1) * 8;
    const int vWof = (lane >> 4) * 4;

    float o[8][4];
    #pragma unroll
    for (int nt = 0; nt < 8; nt++)
        #pragma unroll
        for (int e = 0; e < 4; e++) o[nt][e] = 0.f;
    float m0 = -FLT_MAX, m1 = -FLT_MAX, l0 = 0.f, l1 = 0.f;

    const int ktEnd = qt;     // causal: k tiles 0..qt for q rows [qt*64, qt*64+63]
    for (int kt = 0; kt <= ktEnd; kt++) {
        // mask -> S accumulators via LDG.128 (issued before the K/V wait)
        float s[8][4];
        const float* M0 = Mb + (size_t)(rw+g)*SEQ + kt*64;
        const float* M1 = M0 + (size_t)8*SEQ;
        #pragma unroll
        for (int ntp = 0; ntp < 4; ntp++) {
            float4 u = *(const float4*)(M0 + ntp*16 + tg*4);
            float4 w = *(const float4*)(M1 + ntp*16 + tg*4);
            s[2*ntp  ][0] = u.x; s[2*ntp  ][1] = u.y;
            s[2*ntp+1][0] = u.z; s[2*ntp+1][1] = u.w;
            s[2*ntp  ][2] = w.x; s[2*ntp  ][3] = w.y;
            s[2*ntp+1][2] = w.z; s[2*ntp+1][3] = w.w;
        }

        CP_WAIT0();
        __syncthreads();
        if (kt < ktEnd) KV_ISSUE(kt + 1, (kt + 1) & 1);

        const uint32_t kbase = sb + ((kt & 1)*KV_STAGE)*4;
        const uint32_t vbase = sb + (VS_BASE + (kt & 1)*KV_STAGE)*4;

        #pragma unroll
        for (int ntp = 0; ntp < 4; ntp++) {
            #pragma unroll
            for (int kk = 0; kk < 4; kk++) {
                uint32_t r0, r1, r2, r3;
                uint32_t ka = kbase + ((ntp*16 + kRow)*KVW + kk*8 + kWof)*4;
                LDSM_X4(r0, r1, r2, r3, ka);
                mma16(s[2*ntp  ], qa[kk][0],qa[kk][1],qa[kk][2],qa[kk][3], r0, r1);
                mma16(s[2*ntp+1], qa[kk][0],qa[kk][1],qa[kk][2],qa[kk][3], r2, r3);
            }
        }

        float rm0 = -FLT_MAX, rm1 = -FLT_MAX;
        #pragma unroll
        for (int nt = 0; nt < 8; nt++) {
            rm0 = fmaxf(rm0, fmaxf(s[nt][0], s[nt][1]));
            rm1 = fmaxf(rm1, fmaxf(s[nt][2], s[nt][3]));
        }
        rm0 = fmaxf(rm0, __shfl_xor_sync(0xffffffffu, rm0, 1));
        rm0 = fmaxf(rm0, __shfl_xor_sync(0xffffffffu, rm0, 2));
        rm1 = fmaxf(rm1, __shfl_xor_sync(0xffffffffu, rm1, 1));
        rm1 = fmaxf(rm1, __shfl_xor_sync(0xffffffffu, rm1, 2));

        float mn0 = fmaxf(m0, rm0), mn1 = fmaxf(m1, rm1);
        float f0 = __expf(m0 - mn0), f1 = __expf(m1 - mn1);
        m0 = mn0; m1 = mn1;

        // exp via ex2.approx.f16x2 (2 values per MUFU op); sums in fp32
        const float L2E = 1.44269504088896f;
        float mb0 = mn0 * L2E, mb1 = mn1 * L2E;
        uint32_t P0[8], P1[8];
        float rs0 = 0.f, rs1 = 0.f;
        #pragma unroll
        for (int nt = 0; nt < 8; nt++) {
            float u0 = fmaf(s[nt][0], L2E, -mb0);
            float u1 = fmaf(s[nt][1], L2E, -mb0);
            float u2 = fmaf(s[nt][2], L2E, -mb1);
            float u3 = fmaf(s[nt][3], L2E, -mb1);
            uint32_t h01 = h2pack(u0, u1);
            uint32_t h23 = h2pack(u2, u3);
            asm("ex2.approx.f16x2 %0, %1;" : "=r"(P0[nt]) : "r"(h01));
            asm("ex2.approx.f16x2 %0, %1;" : "=r"(P1[nt]) : "r"(h23));
            __half2 e01 = *(__half2*)&P0[nt];
            __half2 e23 = *(__half2*)&P1[nt];
            rs0 += __low2float(e01) + __high2float(e01);
            rs1 += __low2float(e23) + __high2float(e23);
        }
        l0 = l0*f0 + rs0;
        l1 = l1*f1 + rs1;
        #pragma unroll
        for (int nt = 0; nt < 8; nt++) {
            o[nt][0] *= f0; o[nt][1] *= f0;
            o[nt][2] *= f1; o[nt][3] *= f1;
        }

        // O += P V : P already packed as half2 in P0/P1
        #pragma unroll
        for (int kk = 0; kk < 4; kk++) {
            uint32_t a0 = P0[2*kk  ];
            uint32_t a1 = P1[2*kk  ];
            uint32_t a2 = P0[2*kk+1];
            uint32_t a3 = P1[2*kk+1];
            #pragma unroll
            for (int ntp = 0; ntp < 4; ntp++) {
                uint32_t r0, r1, r2, r3;
                uint32_t va = vbase + ((kk*16 + vRow)*KVW + ntp*8 + vWof)*4;
                LDSM_X4T(r0, r1, r2, r3, va);
                mma16(o[2*ntp  ], a0, a1, a2, a3, r0, r1);
                mma16(o[2*ntp+1], a0, a1, a2, a3, r2, r3);
            }
        }
    }

    l0 += __shfl_xor_sync(0xffffffffu, l0, 1);
    l0 += __shfl_xor_sync(0xffffffffu, l0, 2);
    l1 += __shfl_xor_sync(0xffffffffu, l1, 1);
    l1 += __shfl_xor_sync(0xffffffffu, l1, 2);
    float inv0 = 1.f / l0, inv1 = 1.f / l1;

    int r0 = qt*FB + rw + g, r1 = r0 + 8;
    __half* y0 = g_y + (size_t)(b*SEQ + r0)*CDIM + h*HDIM;
    __half* y1 = g_y + (size_t)(b*SEQ + r1)*CDIM + h*HDIM;
    #pragma unroll
    for (int nt = 0; nt < 8; nt++) {
        int c = nt*8 + tg*2;
        *(uint32_t*)(y0 + c) = h2pack(o[nt][0]*inv0, o[nt][1]*inv0);
        *(uint32_t*)(y1 + c) = h2pack(o[nt][2]*inv1, o[nt][3]*inv1);
    }
}

// ===================== host =================================================
extern "C" void kernel_launch(void* const* d_in, const int* in_sizes, int n_in,
                              void* d_out, int out_size) {
    const float* x      = (const float*)d_in[0];
    const float* mask   = (const float*)d_in[1];
    const float* W_attn = (const float*)d_in[2];
    const float* b_attn = (const float*)d_in[3];
    const float* W_proj = (const float*)d_in[4];
    const float* b_proj = (const float*)d_in[5];
    float* out = (float*)d_out;

    cudaFuncSetAttribute((const void*)flash_attn,
                         cudaFuncAttributeMaxDynamicSharedMemorySize, FLASH_SMEM);
    cudaFuncSetAttribute((const void*)qkv_gemm,
                         cudaFuncAttributeMaxDynamicSharedMemorySize, G_SMEM);
    cudaFuncSetAttribute((const void*)proj_gemm,
                         cudaFuncAttributeMaxDynamicSharedMemorySize, G_SMEM);

    prep_all<<<XB + WAB + WPB, 256>>>(x, W_attn, W_proj);

    dim3 g1(CDIM3/128, MROWS/128);     // 18 x 64
    qkv_gemm<<<g1, 256, G_SMEM>>>(b_attn);

    dim3 g2(SEQ/FB, NHEAD*NB);         // 32 x 48 (h-major: mask L2 reuse over b)
    flash_attn<<<g2, 128, FLASH_SMEM>>>(mask);

    dim3 g3(CDIM/128, MROWS/128);      // 6 x 64
    proj_gemm<<<g3, 256, G_SMEM>>>(b_proj, out);
}

// round 14
// speedup vs baseline: 1.0603x; 1.0603x over previous
#include <cuda_runtime.h>
#include <cuda_fp16.h>
#include <cstdint>
#include <cfloat>

#define NHEAD 12
#define NB    4
#define SEQ   2048
#define HDIM  64
#define CDIM  768
#define CDIM3 2304
#define MROWS (NB*SEQ)   // 8192

// fp16 scratch (static device globals: no runtime allocation)
__device__ __align__(16) __half g_q[NB*NHEAD*SEQ*HDIM];  // q pre-scaled by 0.125
__device__ __align__(16) __half g_k[NB*NHEAD*SEQ*HDIM];
__device__ __align__(16) __half g_v[NB*NHEAD*SEQ*HDIM];
__device__ __align__(16) __half g_y[MROWS*CDIM];
__device__ __align__(16) __half g_xh[MROWS*CDIM];        // x fp16
__device__ __align__(16) __half g_wah[CDIM3*CDIM];       // W_attn^T fp16 [n][k]
__device__ __align__(16) __half g_wph[CDIM*CDIM];        // W_proj^T fp16 [n][k]

__device__ __forceinline__ uint32_t h2pack(float lo, float hi) {
    uint32_t u;
    asm("cvt.rn.f16x2.f32 %0, %1, %2;" : "=r"(u) : "f"(hi), "f"(lo));
    return u;
}

__device__ __forceinline__ uint32_t smem_u32(const void* p) {
    uint32_t a;
    asm("{ .reg .u64 t; cvta.to.shared.u64 t, %1; cvt.u32.u64 %0, t; }"
        : "=r"(a) : "l"(p));
    return a;
}

#define CP16(dst, src) \
    asm volatile("cp.async.cg.shared.global [%0], [%1], 16;" \
                 :: "r"((uint32_t)(dst)), "l"((size_t)(src)) : "memory")
#define CP16A(dst, src) \
    asm volatile("cp.async.ca.shared.global [%0], [%1], 16;" \
                 :: "r"((uint32_t)(dst)), "l"((size_t)(src)) : "memory")
#define CP_COMMIT() asm volatile("cp.async.commit_group;" ::: "memory")
#define CP_WAIT0()  asm volatile("cp.async.wait_group 0;" ::: "memory")

__device__ __forceinline__ void mma16(float* d,
    uint32_t a0, uint32_t a1, uint32_t a2, uint32_t a3,
    uint32_t b0, uint32_t b1) {
    asm volatile(
      "mma.sync.aligned.m16n8k16.row.col.f32.f16.f16.f32 "
      "{%0,%1,%2,%3}, {%4,%5,%6,%7}, {%8,%9}, {%0,%1,%2,%3};\n"
      : "+f"(d[0]), "+f"(d[1]), "+f"(d[2]), "+f"(d[3])
      : "r"(a0), "r"(a1), "r"(a2), "r"(a3), "r"(b0), "r"(b1));
}

#define LDSM_X4(r0,r1,r2,r3,addr) \
    asm volatile("ldmatrix.sync.aligned.m8n8.x4.shared.b16 {%0,%1,%2,%3}, [%4];" \
        : "=r"(r0), "=r"(r1), "=r"(r2), "=r"(r3) : "r"(addr))
#define LDSM_X4T(r0,r1,r2,r3,addr) \
    asm volatile("ldmatrix.sync.aligned.m8n8.x4.trans.shared.b16 {%0,%1,%2,%3}, [%4];" \
        : "=r"(r0), "=r"(r1), "=r"(r2), "=r"(r3) : "r"(addr))

// ===================== merged prep kernel ===================================
#define XB  (MROWS*CDIM/1024)            // 6144
#define WAB ((CDIM3/32)*(CDIM/32))       // 1728
#define WPB ((CDIM/32)*(CDIM/32))        // 576

__global__ __launch_bounds__(256) void prep_all(
    const float* __restrict__ x,
    const float* __restrict__ W_attn,
    const float* __restrict__ W_proj) {
    __shared__ float t[32][33];
    int bx = blockIdx.x;
    if (bx < XB) {
        size_t i = ((size_t)bx * 256 + threadIdx.x) * 4;
        float4 v = *(const float4*)(x + i);
        uint2 o;
        o.x = h2pack(v.x, v.y);
        o.y = h2pack(v.z, v.w);
        *(uint2*)(g_xh + i) = o;
        return;
    }
    const float* src; __half* dst; int K, N, b;
    if (bx < XB + WAB) {
        b = bx - XB; src = W_attn; dst = g_wah; K = CDIM; N = CDIM3;
    } else {
        b = bx - XB - WAB; src = W_proj; dst = g_wph; K = CDIM; N = CDIM;
    }
    int nb = (b % (N/32)) * 32, kb = (b / (N/32)) * 32;
    int tx = threadIdx.x & 31, ty = threadIdx.x >> 5;
    #pragma unroll
    for (int r = 0; r < 4; r++)
        t[ty + r*8][tx] = src[(size_t)(kb + ty + r*8) * N + nb + tx];
    __syncthreads();
    #pragma unroll
    for (int r = 0; r < 4; r++)
        dst[(size_t)(nb + ty + r*8) * K + kb + tx] = __float2half_rn(t[tx][ty + r*8]);
}

// ===================== fp16 GEMM core (128x128x64, cp.async 2-stage) ========
// A loads .ca (L1: tight panel reuse across column-blocks); B loads .cg
// (weights fit in L2 entirely; keeping them out of L1 preserves A lines).
#define GP 36                 // smem pitch in words (64 halves + 4 pad words)
#define ABS (128*GP)          // words per tile array
#define G_SMEM (2*2*ABS*4)    // 73728 B

#define GEMM_LANE_SETUP() \
    const int tid = threadIdx.x; \
    const int wid = tid >> 5, lane = tid & 31; \
    const int g = lane >> 2, tg = lane & 3; \
    const int wM = wid & 3, wN = wid >> 2; \
    const int aRow = (lane & 7) + ((lane >> 3) & 1) * 8, aWof = (lane >> 4) * 4; \
    const int bRow = (lane & 7) + ((lane >> 4) & 1) * 8, bWof = ((lane >> 3) & 1) * 4; \
    const int lrow = tid >> 3, lseg = tid & 7;

#define GEMM_ISSUE(kb, st) do { \
    size_t ko_ = (size_t)(kb)*64*2; \
    uint32_t ad_ = sb + ((st)*2*ABS)*4; \
    uint32_t bd_ = sb + ((st)*2*ABS + ABS)*4; \
    _Pragma("unroll") \
    for (int j_ = 0; j_ < 4; j_++) { \
        CP16A(ad_ + (((lrow + j_*32)*GP + lseg*4))*4, aG + (size_t)(j_*32)*CDIM*2 + ko_); \
        CP16 (bd_ + (((lrow + j_*32)*GP + lseg*4))*4, bG + (size_t)(j_*32)*CDIM*2 + ko_); \
    } \
    CP_COMMIT(); \
} while (0)

#define GEMM_MAINLOOP() \
    float acc[2][8][4]; \
    _Pragma("unroll") \
    for (int i = 0; i < 2; i++) \
        _Pragma("unroll") \
        for (int j = 0; j < 8; j++) \
            _Pragma("unroll") \
            for (int e = 0; e < 4; e++) acc[i][j][e] = 0.f; \
    GEMM_ISSUE(0, 0); \
    for (int kb = 0; kb < CDIM/64; kb++) { \
        CP_WAIT0(); \
        __syncthreads(); \
        if (kb + 1 < CDIM/64) GEMM_ISSUE(kb + 1, (kb + 1) & 1); \
        const uint32_t sbA = sb + ((kb & 1)*2*ABS)*4; \
        const uint32_t sbB = sbA + ABS*4; \
        _Pragma("unroll") \
        for (int kk = 0; kk < 4; kk++) { \
            uint32_t a0[4], a1[4]; \
            LDSM_X4(a0[0],a0[1],a0[2],a0[3], sbA + ((wM*32      + aRow)*GP + kk*8 + aWof)*4); \
            LDSM_X4(a1[0],a1[1],a1[2],a1[3], sbA + ((wM*32 + 16 + aRow)*GP + kk*8 + aWof)*4); \
            _Pragma("unroll") \
            for (int ntp = 0; ntp < 4; ntp++) { \
                uint32_t b0, b1, b2, b3; \
                LDSM_X4(b0, b1, b2, b3, \
                        sbB + ((wN*64 + ntp*16 + bRow)*GP + kk*8 + bWof)*4); \
                mma16(acc[0][2*ntp  ], a0[0],a0[1],a0[2],a0[3], b0, b1); \
                mma16(acc[0][2*ntp+1], a0[0],a0[1],a0[2],a0[3], b2, b3); \
                mma16(acc[1][2*ntp  ], a1[0],a1[1],a1[2],a1[3], b0, b1); \
                mma16(acc[1][2*ntp+1], a1[0],a1[1],a1[2],a1[3], b2, b3); \
            } \
        } \
        __syncthreads(); \
    }

// ---------------------------------------------------------------------------
// Kernel 1: qkv = xh @ wah^T + b_attn -> fp16 head-major q/k/v (q * 0.125)
// ---------------------------------------------------------------------------
__global__ __launch_bounds__(256) void qkv_gemm(const float* __restrict__ bias) {
    extern __shared__ uint32_t smw[];
    uint32_t sb = smem_u32(smw);
    GEMM_LANE_SETUP();
    const int rowBase = blockIdx.y * 128;
    const int colBase = blockIdx.x * 128;
    const size_t aG = __cvta_generic_to_global(g_xh  + (size_t)(rowBase + lrow)*CDIM + lseg*8);
    const size_t bG = __cvta_generic_to_global(g_wah + (size_t)(colBase + lrow)*CDIM + lseg*8);

    GEMM_MAINLOOP();

    const int which = colBase / CDIM;
    const int cjBase = colBase % CDIM;
    __half* dst = (which == 0) ? g_q : (which == 1 ? g_k : g_v);
    const float qs = (which == 0) ? 0.125f : 1.0f;

    #pragma unroll
    for (int mt = 0; mt < 2; mt++) {
        int r0g = rowBase + wM*32 + mt*16 + g;
        int r1g = r0g + 8;
        int b0i = r0g >> 11, t0 = r0g & 2047;
        int b1i = r1g >> 11, t1 = r1g & 2047;
        #pragma unroll
        for (int nt = 0; nt < 8; nt++) {
            int cj = cjBase + wN*64 + nt*8 + tg*2;
            int h = cj >> 6, d = cj & 63;
            int n = colBase + wN*64 + nt*8 + tg*2;
            float bb0 = bias[n], bb1 = bias[n+1];
            size_t o0 = ((size_t)(b0i*NHEAD + h)*SEQ + t0)*HDIM + d;
            size_t o1 = ((size_t)(b1i*NHEAD + h)*SEQ + t1)*HDIM + d;
            *(uint32_t*)(dst + o0) =
                h2pack((acc[mt][nt][0] + bb0)*qs, (acc[mt][nt][1] + bb1)*qs);
            *(uint32_t*)(dst + o1) =
                h2pack((acc[mt][nt][2] + bb0)*qs, (acc[mt][nt][3] + bb1)*qs);
        }
    }
}

// ---------------------------------------------------------------------------
// Kernel 3: out = y(fp16) @ wph^T + b_proj, fp32 out
// ---------------------------------------------------------------------------
__global__ __launch_bounds__(256) void proj_gemm(const float* __restrict__ bias,
                                                 float* __restrict__ out) {
    extern __shared__ uint32_t smw[];
    uint32_t sb = smem_u32(smw);
    GEMM_LANE_SETUP();
    const int rowBase = blockIdx.y * 128;
    const int colBase = blockIdx.x * 128;
    const size_t aG = __cvta_generic_to_global(g_y   + (size_t)(rowBase + lrow)*CDIM + lseg*8);
    const size_t bG = __cvta_generic_to_global(g_wph + (size_t)(colBase + lrow)*CDIM + lseg*8);

    GEMM_MAINLOOP();

    #pragma unroll
    for (int mt = 0; mt < 2; mt++) {
        int r0g = rowBase + wM*32 + mt*16 + g;
        int r1g = r0g + 8;
        #pragma unroll
        for (int nt = 0; nt < 8; nt++) {
            int n = colBase + wN*64 + nt*8 + tg*2;
            float bb0 = bias[n], bb1 = bias[n+1];
            float2 u0 = {acc[mt][nt][0] + bb0, acc[mt][nt][1] + bb1};
            float2 u1 = {acc[mt][nt][2] + bb0, acc[mt][nt][3] + bb1};
            *(float2*)(out + (size_t)r0g*CDIM + n) = u0;
            *(float2*)(out + (size_t)r1g*CDIM + n) = u1;
        }
    }
}

// ---------------------------------------------------------------------------
// Kernel 2: fp16 flash attention — R12-exact (Br=128, 8 warps, 2 CTAs/SM,
// 2-stage cp.async, f16x2 ex2 softmax, K/V row permutation -> LDG.128 mask).
// ---------------------------------------------------------------------------
#define KVW 36
#define KV_STAGE (64*KVW)
#define VS_BASE  (2*KV_STAGE)
#define FLASH_SMEM ((4*KV_STAGE)*4)    // 36864 B

__global__ __launch_bounds__(256, 2) void flash_attn(const float* __restrict__ mask) {
    extern __shared__ uint32_t sm[];
    uint32_t sb = smem_u32(sm);

    const int tid = threadIdx.x;
    const int wid = tid >> 5, lane = tid & 31;
    const int g = lane >> 2, tg = lane & 3;
    const int qt = (int)(gridDim.x - 1 - blockIdx.x);
    const int h = blockIdx.y >> 2, b = blockIdx.y & 3;
    const int rw = wid * 16;

    const __half* Qg  = g_q + ((size_t)((b*NHEAD + h)*SEQ) + qt*128)*HDIM;
    const __half* Kg0 = g_k + (size_t)((b*NHEAD + h)*SEQ)*HDIM;
    const __half* Vg0 = g_v + (size_t)((b*NHEAD + h)*SEQ)*HDIM;
    const float*  Mb  = mask + ((size_t)h*SEQ + qt*128)*SEQ;

    // physical smem row = crow; global source row = perm(crow)
    const int crow = tid >> 2, cc0 = tid & 3;
    const int p15 = crow & 15;
    const int l15 = (p15 < 8) ? ((p15 >> 1)*4 + (p15 & 1))
                              : (((p15 - 8) >> 1)*4 + 2 + (p15 & 1));
    const int lsrc = (crow & ~15) | l15;
    const size_t ksrc0 = __cvta_generic_to_global(Kg0 + (size_t)lsrc*HDIM);
    const size_t vsrc0 = __cvta_generic_to_global(Vg0 + (size_t)lsrc*HDIM);
    const uint32_t kdst0 = sb + crow*KVW*4;
    const uint32_t vdst0 = sb + (VS_BASE + crow*KVW)*4;

    #define KV_ISSUE(kt, st) do { \
        size_t ks_ = ksrc0 + (size_t)(kt)*64*HDIM*2; \
        size_t vs_ = vsrc0 + (size_t)(kt)*64*HDIM*2; \
        uint32_t kd_ = kdst0 + (st)*KV_STAGE*4; \
        uint32_t vd_ = vdst0 + (st)*KV_STAGE*4; \
        _Pragma("unroll") \
        for (int j_ = 0; j_ < 2; j_++) { \
            CP16(kd_ + (cc0 + 4*j_)*16, ks_ + (cc0 + 4*j_)*16); \
            CP16(vd_ + (cc0 + 4*j_)*16, vs_ + (cc0 + 4*j_)*16); \
        } \
        CP_COMMIT(); \
    } while (0)

    KV_ISSUE(0, 0);

    uint32_t qa[4][4];
    {
        const uint32_t* q0 = (const uint32_t*)(Qg + (size_t)(rw+g)*HDIM);
        const uint32_t* q1 = (const uint32_t*)(Qg + (size_t)(rw+8+g)*HDIM);
        #pragma unroll
        for (int kk = 0; kk < 4; kk++) {
            qa[kk][0] = q0[kk*8 + tg];
            qa[kk][1] = q1[kk*8 + tg];
            qa[kk][2] = q0[kk*8 + tg + 4];
            qa[kk][3] = q1[kk*8 + tg + 4];
        }
    }

    const int kRow = (lane & 7) + ((lane >> 4) & 1) * 8;
    const int kWof = ((lane >> 3) & 1) * 4;
    const int vRow = (lane & 7) + ((lane >> 3) & 1) * 8;
    const int vWof = (lane >> 4) * 4;

    float o[8][4];
    #pragma unroll
    for (int nt = 0; nt < 8; nt++)
        #pragma unroll
        for (int e = 0; e < 4; e++) o[nt][e] = 0.f;
    float m0 = -FLT_MAX, m1 = -FLT_MAX, l0 = 0.f, l1 = 0.f;

    const int ktEnd = 2*qt + 1;
    for (int kt = 0; kt <= ktEnd; kt++) {
        // mask -> S accumulators via LDG.128 (issued before the K/V wait)
        float s[8][4];
        const float* M0 = Mb + (size_t)(rw+g)*SEQ + kt*64;
        const float* M1 = M0 + (size_t)8*SEQ;
        #pragma unroll
        for (int ntp = 0; ntp < 4; ntp++) {
            float4 u = *(const float4*)(M0 + ntp*16 + tg*4);
            float4 w = *(const float4*)(M1 + ntp*16 + tg*4);
            s[2*ntp  ][0] = u.x; s[2*ntp  ][1] = u.y;
            s[2*ntp+1][0] = u.z; s[2*ntp+1][1] = u.w;
            s[2*ntp  ][2] = w.x; s[2*ntp  ][3] = w.y;
            s[2*ntp+1][2] = w.z; s[2*ntp+1][3] = w.w;
        }

        CP_WAIT0();
        __syncthreads();
        if (kt < ktEnd) KV_ISSUE(kt + 1, (kt + 1) & 1);

        const uint32_t kbase = sb + ((kt & 1)*KV_STAGE)*4;
        const uint32_t vbase = sb + (VS_BASE + (kt & 1)*KV_STAGE)*4;

        #pragma unroll
        for (int ntp = 0; ntp < 4; ntp++) {
            #pragma unroll
            for (int kk = 0; kk < 4; kk++) {
                uint32_t r0, r1, r2, r3;
                uint32_t ka = kbase + ((ntp*16 + kRow)*KVW + kk*8 + kWof)*4;
                LDSM_X4(r0, r1, r2, r3, ka);
                mma16(s[2*ntp  ], qa[kk][0],qa[kk][1],qa[kk][2],qa[kk][3], r0, r1);
                mma16(s[2*ntp+1], qa[kk][0],qa[kk][1],qa[kk][2],qa[kk][3], r2, r3);
            }
        }

        float rm0 = -FLT_MAX, rm1 = -FLT_MAX;
        #pragma unroll
        for (int nt = 0; nt < 8; nt++) {
            rm0 = fmaxf(rm0, fmaxf(s[nt][0], s[nt][1]));
            rm1 = fmaxf(rm1, fmaxf(s[nt][2], s[nt][3]));
        }
        rm0 = fmaxf(rm0, __shfl_xor_sync(0xffffffffu, rm0, 1));
        rm0 = fmaxf(rm0, __shfl_xor_sync(0xffffffffu, rm0, 2));
        rm1 = fmaxf(rm1, __shfl_xor_sync(0xffffffffu, rm1, 1));
        rm1 = fmaxf(rm1, __shfl_xor_sync(0xffffffffu, rm1, 2));

        float mn0 = fmaxf(m0, rm0), mn1 = fmaxf(m1, rm1);
        float f0 = __expf(m0 - mn0), f1 = __expf(m1 - mn1);
        m0 = mn0; m1 = mn1;

        // exp via ex2.approx.f16x2 (2 values per MUFU op); sums in fp32
        const float L2E = 1.44269504088896f;
        float mb0 = mn0 * L2E, mb1 = mn1 * L2E;
        uint32_t P0[8], P1[8];
        float rs0 = 0.f, rs1 = 0.f;
        #pragma unroll
        for (int nt = 0; nt < 8; nt++) {
            float u0 = fmaf(s[nt][0], L2E, -mb0);
            float u1 = fmaf(s[nt][1], L2E, -mb0);
            float u2 = fmaf(s[nt][2], L2E, -mb1);
            float u3 = fmaf(s[nt][3], L2E, -mb1);
            uint32_t h01 = h2pack(u0, u1);
            uint32_t h23 = h2pack(u2, u3);
            asm("ex2.approx.f16x2 %0, %1;" : "=r"(P0[nt]) : "r"(h01));
            asm("ex2.approx.f16x2 %0, %1;" : "=r"(P1[nt]) : "r"(h23));
            __half2 e01 = *(__half2*)&P0[nt];
            __half2 e23 = *(__half2*)&P1[nt];
            rs0 += __low2float(e01) + __high2float(e01);
            rs1 += __low2float(e23) + __high2float(e23);
        }
        l0 = l0*f0 + rs0;
        l1 = l1*f1 + rs1;
        #pragma unroll
        for (int nt = 0; nt < 8; nt++) {
            o[nt][0] *= f0; o[nt][1] *= f0;
            o[nt][2] *= f1; o[nt][3] *= f1;
        }

        // O += P V : P already packed as half2 in P0/P1
        #pragma unroll
        for (int kk = 0; kk < 4; kk++) {
            uint32_t a0 = P0[2*kk  ];
            uint32_t a1 = P1[2*kk  ];
            uint32_t a2 = P0[2*kk+1];
            uint32_t a3 = P1[2*kk+1];
            #pragma unroll
            for (int ntp = 0; ntp < 4; ntp++) {
                uint32_t r0, r1, r2, r3;
                uint32_t va = vbase + ((kk*16 + vRow)*KVW + ntp*8 + vWof)*4;
                LDSM_X4T(r0, r1, r2, r3, va);
                mma16(o[2*ntp  ], a0, a1, a2, a3, r0, r1);
                mma16(o[2*ntp+1], a0, a1, a2, a3, r2, r3);
            }
        }
    }

    l0 += __shfl_xor_sync(0xffffffffu, l0, 1);
    l0 += __shfl_xor_sync(0xffffffffu, l0, 2);
    l1 += __shfl_xor_sync(0xffffffffu, l1, 1);
    l1 += __shfl_xor_sync(0xffffffffu, l1, 2);
    float inv0 = 1.f / l0, inv1 = 1.f / l1;

    int r0 = qt*128 + rw + g, r1 = r0 + 8;
    __half* y0 = g_y + (size_t)(b*SEQ + r0)*CDIM + h*HDIM;
    __half* y1 = g_y + (size_t)(b*SEQ + r1)*CDIM + h*HDIM;
    #pragma unroll
    for (int nt = 0; nt < 8; nt++) {
        int c = nt*8 + tg*2;
        *(uint32_t*)(y0 + c) = h2pack(o[nt][0]*inv0, o[nt][1]*inv0);
        *(uint32_t*)(y1 + c) = h2pack(o[nt][2]*inv1, o[nt][3]*inv1);
    }
}

// ===================== host =================================================
extern "C" void kernel_launch(void* const* d_in, const int* in_sizes, int n_in,
                              void* d_out, int out_size) {
    const float* x      = (const float*)d_in[0];
    const float* mask   = (const float*)d_in[1];
    const float* W_attn = (const float*)d_in[2];
    const float* b_attn = (const float*)d_in[3];
    const float* W_proj = (const float*)d_in[4];
    const float* b_proj = (const float*)d_in[5];
    float* out = (float*)d_out;

    cudaFuncSetAttribute((const void*)flash_attn,
                         cudaFuncAttributeMaxDynamicSharedMemorySize, FLASH_SMEM);
    cudaFuncSetAttribute((const void*)qkv_gemm,
                         cudaFuncAttributeMaxDynamicSharedMemorySize, G_SMEM);
    cudaFuncSetAttribute((const void*)proj_gemm,
                         cudaFuncAttributeMaxDynamicSharedMemorySize, G_SMEM);

    prep_all<<<XB + WAB + WPB, 256>>>(x, W_attn, W_proj);

    dim3 g1(CDIM3/128, MROWS/128);     // 18 x 64
    qkv_gemm<<<g1, 256, G_SMEM>>>(b_attn);

    dim3 g2(SEQ/128, NHEAD*NB);        // 16 x 48 (h-major: mask L2 reuse over b)
    flash_attn<<<g2, 256, FLASH_SMEM>>>(mask);

    dim3 g3(CDIM/128, MROWS/128);      // 6 x 64
    proj_gemm<<<g3, 256, G_SMEM>>>(b_proj, out);
}

// round 15
// speedup vs baseline: 1.0665x; 1.0058x over previous
#include <cuda_runtime.h>
#include <cuda_fp16.h>
#include <cstdint>
#include <cfloat>

#define NHEAD 12
#define NB    4
#define SEQ   2048
#define HDIM  64
#define CDIM  768
#define CDIM3 2304
#define MROWS (NB*SEQ)   // 8192

// fp16 scratch (static device globals: no runtime allocation)
__device__ __align__(16) __half g_q[NB*NHEAD*SEQ*HDIM];  // q pre-scaled by 0.125
__device__ __align__(16) __half g_k[NB*NHEAD*SEQ*HDIM];
__device__ __align__(16) __half g_v[NB*NHEAD*SEQ*HDIM];
__device__ __align__(16) __half g_y[MROWS*CDIM];
__device__ __align__(16) __half g_xh[MROWS*CDIM];        // x fp16
__device__ __align__(16) __half g_wah[CDIM3*CDIM];       // W_attn^T fp16 [n][k]
__device__ __align__(16) __half g_wph[CDIM*CDIM];        // W_proj^T fp16 [n][k]

__device__ __forceinline__ uint32_t h2pack(float lo, float hi) {
    uint32_t u;
    asm("cvt.rn.f16x2.f32 %0, %1, %2;" : "=r"(u) : "f"(hi), "f"(lo));
    return u;
}

__device__ __forceinline__ uint32_t smem_u32(const void* p) {
    uint32_t a;
    asm("{ .reg .u64 t; cvta.to.shared.u64 t, %1; cvt.u32.u64 %0, t; }"
        : "=r"(a) : "l"(p));
    return a;
}

#define CP16(dst, src) \
    asm volatile("cp.async.cg.shared.global [%0], [%1], 16;" \
                 :: "r"((uint32_t)(dst)), "l"((size_t)(src)) : "memory")
#define CP16A(dst, src) \
    asm volatile("cp.async.ca.shared.global [%0], [%1], 16;" \
                 :: "r"((uint32_t)(dst)), "l"((size_t)(src)) : "memory")
#define CP_COMMIT() asm volatile("cp.async.commit_group;" ::: "memory")
#define CP_WAIT0()  asm volatile("cp.async.wait_group 0;" ::: "memory")

__device__ __forceinline__ void mma16(float* d,
    uint32_t a0, uint32_t a1, uint32_t a2, uint32_t a3,
    uint32_t b0, uint32_t b1) {
    asm volatile(
      "mma.sync.aligned.m16n8k16.row.col.f32.f16.f16.f32 "
      "{%0,%1,%2,%3}, {%4,%5,%6,%7}, {%8,%9}, {%0,%1,%2,%3};\n"
      : "+f"(d[0]), "+f"(d[1]), "+f"(d[2]), "+f"(d[3])
      : "r"(a0), "r"(a1), "r"(a2), "r"(a3), "r"(b0), "r"(b1));
}

#define LDSM_X4(r0,r1,r2,r3,addr) \
    asm volatile("ldmatrix.sync.aligned.m8n8.x4.shared.b16 {%0,%1,%2,%3}, [%4];" \
        : "=r"(r0), "=r"(r1), "=r"(r2), "=r"(r3) : "r"(addr))
#define LDSM_X4T(r0,r1,r2,r3,addr) \
    asm volatile("ldmatrix.sync.aligned.m8n8.x4.trans.shared.b16 {%0,%1,%2,%3}, [%4];" \
        : "=r"(r0), "=r"(r1), "=r"(r2), "=r"(r3) : "r"(addr))

// ===================== merged prep kernel ===================================
#define XB  (MROWS*CDIM/1024)            // 6144
#define WAB ((CDIM3/32)*(CDIM/32))       // 1728
#define WPB ((CDIM/32)*(CDIM/32))        // 576

__global__ __launch_bounds__(256) void prep_all(
    const float* __restrict__ x,
    const float* __restrict__ W_attn,
    const float* __restrict__ W_proj) {
    __shared__ float t[32][33];
    int bx = blockIdx.x;
    if (bx < XB) {
        size_t i = ((size_t)bx * 256 + threadIdx.x) * 4;
        float4 v = *(const float4*)(x + i);
        uint2 o;
        o.x = h2pack(v.x, v.y);
        o.y = h2pack(v.z, v.w);
        *(uint2*)(g_xh + i) = o;
        return;
    }
    const float* src; __half* dst; int K, N, b;
    if (bx < XB + WAB) {
        b = bx - XB; src = W_attn; dst = g_wah; K = CDIM; N = CDIM3;
    } else {
        b = bx - XB - WAB; src = W_proj; dst = g_wph; K = CDIM; N = CDIM;
    }
    int nb = (b % (N/32)) * 32, kb = (b / (N/32)) * 32;
    int tx = threadIdx.x & 31, ty = threadIdx.x >> 5;
    #pragma unroll
    for (int r = 0; r < 4; r++)
        t[ty + r*8][tx] = src[(size_t)(kb + ty + r*8) * N + nb + tx];
    __syncthreads();
    #pragma unroll
    for (int r = 0; r < 4; r++)
        dst[(size_t)(nb + ty + r*8) * K + kb + tx] = __float2half_rn(t[tx][ty + r*8]);
}

// ===================== fp16 GEMM core (128x128x64, cp.async 2-stage) ========
// All cp.async loads .ca (R14: .cg on either operand regressed).
// B fragments double-buffered in registers: frags for kk+1 load while the
// 16 MMAs of kk execute, hiding the ldmatrix latency within one warp.
#define GP 36                 // smem pitch in words (64 halves + 4 pad words)
#define ABS (128*GP)          // words per tile array
#define G_SMEM (2*2*ABS*4)    // 73728 B

#define GEMM_LANE_SETUP() \
    const int tid = threadIdx.x; \
    const int wid = tid >> 5, lane = tid & 31; \
    const int g = lane >> 2, tg = lane & 3; \
    const int wM = wid & 3, wN = wid >> 2; \
    const int aRow = (lane & 7) + ((lane >> 3) & 1) * 8, aWof = (lane >> 4) * 4; \
    const int bRow = (lane & 7) + ((lane >> 4) & 1) * 8, bWof = ((lane >> 3) & 1) * 4; \
    const int lrow = tid >> 3, lseg = tid & 7;

#define GEMM_ISSUE(kb, st) do { \
    size_t ko_ = (size_t)(kb)*64*2; \
    uint32_t ad_ = sb + ((st)*2*ABS)*4; \
    uint32_t bd_ = sb + ((st)*2*ABS + ABS)*4; \
    _Pragma("unroll") \
    for (int j_ = 0; j_ < 4; j_++) { \
        CP16A(ad_ + (((lrow + j_*32)*GP + lseg*4))*4, aG + (size_t)(j_*32)*CDIM*2 + ko_); \
        CP16A(bd_ + (((lrow + j_*32)*GP + lseg*4))*4, bG + (size_t)(j_*32)*CDIM*2 + ko_); \
    } \
    CP_COMMIT(); \
} while (0)

#define LOAD_BFRAGS(kk, bi) \
    _Pragma("unroll") \
    for (int ntp_ = 0; ntp_ < 4; ntp_++) { \
        LDSM_X4(bf[bi][4*ntp_], bf[bi][4*ntp_+1], bf[bi][4*ntp_+2], bf[bi][4*ntp_+3], \
                sbB + ((wN*64 + ntp_*16 + bRow)*GP + (kk)*8 + bWof)*4); \
    }

#define GEMM_MAINLOOP() \
    float acc[2][8][4]; \
    _Pragma("unroll") \
    for (int i = 0; i < 2; i++) \
        _Pragma("unroll") \
        for (int j = 0; j < 8; j++) \
            _Pragma("unroll") \
            for (int e = 0; e < 4; e++) acc[i][j][e] = 0.f; \
    GEMM_ISSUE(0, 0); \
    for (int kb = 0; kb < CDIM/64; kb++) { \
        CP_WAIT0(); \
        __syncthreads(); \
        if (kb + 1 < CDIM/64) GEMM_ISSUE(kb + 1, (kb + 1) & 1); \
        const uint32_t sbA = sb + ((kb & 1)*2*ABS)*4; \
        const uint32_t sbB = sbA + ABS*4; \
        uint32_t bf[2][16]; \
        LOAD_BFRAGS(0, 0); \
        _Pragma("unroll") \
        for (int kk = 0; kk < 4; kk++) { \
            uint32_t a0[4], a1[4]; \
            LDSM_X4(a0[0],a0[1],a0[2],a0[3], sbA + ((wM*32      + aRow)*GP + kk*8 + aWof)*4); \
            LDSM_X4(a1[0],a1[1],a1[2],a1[3], sbA + ((wM*32 + 16 + aRow)*GP + kk*8 + aWof)*4); \
            if (kk < 3) { LOAD_BFRAGS(kk + 1, (kk + 1) & 1); } \
            const int cb = kk & 1; \
            _Pragma("unroll") \
            for (int ntp = 0; ntp < 4; ntp++) { \
                mma16(acc[0][2*ntp  ], a0[0],a0[1],a0[2],a0[3], bf[cb][4*ntp  ], bf[cb][4*ntp+1]); \
                mma16(acc[0][2*ntp+1], a0[0],a0[1],a0[2],a0[3], bf[cb][4*ntp+2], bf[cb][4*ntp+3]); \
                mma16(acc[1][2*ntp  ], a1[0],a1[1],a1[2],a1[3], bf[cb][4*ntp  ], bf[cb][4*ntp+1]); \
                mma16(acc[1][2*ntp+1], a1[0],a1[1],a1[2],a1[3], bf[cb][4*ntp+2], bf[cb][4*ntp+3]); \
            } \
        } \
        __syncthreads(); \
    }

// ---------------------------------------------------------------------------
// Kernel 1: qkv = xh @ wah^T + b_attn -> fp16 head-major q/k/v (q * 0.125)
// ---------------------------------------------------------------------------
__global__ __launch_bounds__(256, 2) void qkv_gemm(const float* __restrict__ bias) {
    extern __shared__ uint32_t smw[];
    uint32_t sb = smem_u32(smw);
    GEMM_LANE_SETUP();
    const int rowBase = blockIdx.y * 128;
    const int colBase = blockIdx.x * 128;
    const size_t aG = __cvta_generic_to_global(g_xh  + (size_t)(rowBase + lrow)*CDIM + lseg*8);
    const size_t bG = __cvta_generic_to_global(g_wah + (size_t)(colBase + lrow)*CDIM + lseg*8);

    GEMM_MAINLOOP();

    const int which = colBase / CDIM;
    const int cjBase = colBase % CDIM;
    __half* dst = (which == 0) ? g_q : (which == 1 ? g_k : g_v);
    const float qs = (which == 0) ? 0.125f : 1.0f;

    #pragma unroll
    for (int mt = 0; mt < 2; mt++) {
        int r0g = rowBase + wM*32 + mt*16 + g;
        int r1g = r0g + 8;
        int b0i = r0g >> 11, t0 = r0g & 2047;
        int b1i = r1g >> 11, t1 = r1g & 2047;
        #pragma unroll
        for (int nt = 0; nt < 8; nt++) {
            int cj = cjBase + wN*64 + nt*8 + tg*2;
            int h = cj >> 6, d = cj & 63;
            int n = colBase + wN*64 + nt*8 + tg*2;
            float bb0 = bias[n], bb1 = bias[n+1];
            size_t o0 = ((size_t)(b0i*NHEAD + h)*SEQ + t0)*HDIM + d;
            size_t o1 = ((size_t)(b1i*NHEAD + h)*SEQ + t1)*HDIM + d;
            *(uint32_t*)(dst + o0) =
                h2pack((acc[mt][nt][0] + bb0)*qs, (acc[mt][nt][1] + bb1)*qs);
            *(uint32_t*)(dst + o1) =
                h2pack((acc[mt][nt][2] + bb0)*qs, (acc[mt][nt][3] + bb1)*qs);
        }
    }
}

// ---------------------------------------------------------------------------
// Kernel 3: out = y(fp16) @ wph^T + b_proj, fp32 out
// ---------------------------------------------------------------------------
__global__ __launch_bounds__(256, 2) void proj_gemm(const float* __restrict__ bias,
                                                    float* __restrict__ out) {
    extern __shared__ uint32_t smw[];
    uint32_t sb = smem_u32(smw);
    GEMM_LANE_SETUP();
    const int rowBase = blockIdx.y * 128;
    const int colBase = blockIdx.x * 128;
    const size_t aG = __cvta_generic_to_global(g_y   + (size_t)(rowBase + lrow)*CDIM + lseg*8);
    const size_t bG = __cvta_generic_to_global(g_wph + (size_t)(colBase + lrow)*CDIM + lseg*8);

    GEMM_MAINLOOP();

    #pragma unroll
    for (int mt = 0; mt < 2; mt++) {
        int r0g = rowBase + wM*32 + mt*16 + g;
        int r1g = r0g + 8;
        #pragma unroll
        for (int nt = 0; nt < 8; nt++) {
            int n = colBase + wN*64 + nt*8 + tg*2;
            float bb0 = bias[n], bb1 = bias[n+1];
            float2 u0 = {acc[mt][nt][0] + bb0, acc[mt][nt][1] + bb1};
            float2 u1 = {acc[mt][nt][2] + bb0, acc[mt][nt][3] + bb1};
            *(float2*)(out + (size_t)r0g*CDIM + n) = u0;
            *(float2*)(out + (size_t)r1g*CDIM + n) = u1;
        }
    }
}

// ---------------------------------------------------------------------------
// Kernel 2: fp16 flash attention — R12-exact (Br=128, 8 warps, 2 CTAs/SM,
// 2-stage cp.async, f16x2 ex2 softmax, K/V row permutation -> LDG.128 mask).
// ---------------------------------------------------------------------------
#define KVW 36
#define KV_STAGE (64*KVW)
#define VS_BASE  (2*KV_STAGE)
#define FLASH_SMEM ((4*KV_STAGE)*4)    // 36864 B

__global__ __launch_bounds__(256, 2) void flash_attn(const float* __restrict__ mask) {
    extern __shared__ uint32_t sm[];
    uint32_t sb = smem_u32(sm);

    const int tid = threadIdx.x;
    const int wid = tid >> 5, lane = tid & 31;
    const int g = lane >> 2, tg = lane & 3;
    const int qt = (int)(gridDim.x - 1 - blockIdx.x);
    const int h = blockIdx.y >> 2, b = blockIdx.y & 3;
    const int rw = wid * 16;

    const __half* Qg  = g_q + ((size_t)((b*NHEAD + h)*SEQ) + qt*128)*HDIM;
    const __half* Kg0 = g_k + (size_t)((b*NHEAD + h)*SEQ)*HDIM;
    const __half* Vg0 = g_v + (size_t)((b*NHEAD + h)*SEQ)*HDIM;
    const float*  Mb  = mask + ((size_t)h*SEQ + qt*128)*SEQ;

    // physical smem row = crow; global source row = perm(crow)
    const int crow = tid >> 2, cc0 = tid & 3;
    const int p15 = crow & 15;
    const int l15 = (p15 < 8) ? ((p15 >> 1)*4 + (p15 & 1))
                              : (((p15 - 8) >> 1)*4 + 2 + (p15 & 1));
    const int lsrc = (crow & ~15) | l15;
    const size_t ksrc0 = __cvta_generic_to_global(Kg0 + (size_t)lsrc*HDIM);
    const size_t vsrc0 = __cvta_generic_to_global(Vg0 + (size_t)lsrc*HDIM);
    const uint32_t kdst0 = sb + crow*KVW*4;
    const uint32_t vdst0 = sb + (VS_BASE + crow*KVW)*4;

    #define KV_ISSUE(kt, st) do { \
        size_t ks_ = ksrc0 + (size_t)(kt)*64*HDIM*2; \
        size_t vs_ = vsrc0 + (size_t)(kt)*64*HDIM*2; \
        uint32_t kd_ = kdst0 + (st)*KV_STAGE*4; \
        uint32_t vd_ = vdst0 + (st)*KV_STAGE*4; \
        _Pragma("unroll") \
        for (int j_ = 0; j_ < 2; j_++) { \
            CP16(kd_ + (cc0 + 4*j_)*16, ks_ + (cc0 + 4*j_)*16); \
            CP16(vd_ + (cc0 + 4*j_)*16, vs_ + (cc0 + 4*j_)*16); \
        } \
        CP_COMMIT(); \
    } while (0)

    KV_ISSUE(0, 0);

    uint32_t qa[4][4];
    {
        const uint32_t* q0 = (const uint32_t*)(Qg + (size_t)(rw+g)*HDIM);
        const uint32_t* q1 = (const uint32_t*)(Qg + (size_t)(rw+8+g)*HDIM);
        #pragma unroll
        for (int kk = 0; kk < 4; kk++) {
            qa[kk][0] = q0[kk*8 + tg];
            qa[kk][1] = q1[kk*8 + tg];
            qa[kk][2] = q0[kk*8 + tg + 4];
            qa[kk][3] = q1[kk*8 + tg + 4];
        }
    }

    const int kRow = (lane & 7) + ((lane >> 4) & 1) * 8;
    const int kWof = ((lane >> 3) & 1) * 4;
    const int vRow = (lane & 7) + ((lane >> 3) & 1) * 8;
    const int vWof = (lane >> 4) * 4;

    float o[8][4];
    #pragma unroll
    for (int nt = 0; nt < 8; nt++)
        #pragma unroll
        for (int e = 0; e < 4; e++) o[nt][e] = 0.f;
    float m0 = -FLT_MAX, m1 = -FLT_MAX, l0 = 0.f, l1 = 0.f;

    const int ktEnd = 2*qt + 1;
    for (int kt = 0; kt <= ktEnd; kt++) {
        // mask -> S accumulators via LDG.128 (issued before the K/V wait)
        float s[8][4];
        const float* M0 = Mb + (size_t)(rw+g)*SEQ + kt*64;
        const float* M1 = M0 + (size_t)8*SEQ;
        #pragma unroll
        for (int ntp = 0; ntp < 4; ntp++) {
            float4 u = *(const float4*)(M0 + ntp*16 + tg*4);
            float4 w = *(const float4*)(M1 + ntp*16 + tg*4);
            s[2*ntp  ][0] = u.x; s[2*ntp  ][1] = u.y;
            s[2*ntp+1][0] = u.z; s[2*ntp+1][1] = u.w;
            s[2*ntp  ][2] = w.x; s[2*ntp  ][3] = w.y;
            s[2*ntp+1][2] = w.z; s[2*ntp+1][3] = w.w;
        }

        CP_WAIT0();
        __syncthreads();
        if (kt < ktEnd) KV_ISSUE(kt + 1, (kt + 1) & 1);

        const uint32_t kbase = sb + ((kt & 1)*KV_STAGE)*4;
        const uint32_t vbase = sb + (VS_BASE + (kt & 1)*KV_STAGE)*4;

        #pragma unroll
        for (int ntp = 0; ntp < 4; ntp++) {
            #pragma unroll
            for (int kk = 0; kk < 4; kk++) {
                uint32_t r0, r1, r2, r3;
                uint32_t ka = kbase + ((ntp*16 + kRow)*KVW + kk*8 + kWof)*4;
                LDSM_X4(r0, r1, r2, r3, ka);
                mma16(s[2*ntp  ], qa[kk][0],qa[kk][1],qa[kk][2],qa[kk][3], r0, r1);
                mma16(s[2*ntp+1], qa[kk][0],qa[kk][1],qa[kk][2],qa[kk][3], r2, r3);
            }
        }

        float rm0 = -FLT_MAX, rm1 = -FLT_MAX;
        #pragma unroll
        for (int nt = 0; nt < 8; nt++) {
            rm0 = fmaxf(rm0, fmaxf(s[nt][0], s[nt][1]));
            rm1 = fmaxf(rm1, fmaxf(s[nt][2], s[nt][3]));
        }
        rm0 = fmaxf(rm0, __shfl_xor_sync(0xffffffffu, rm0, 1));
        rm0 = fmaxf(rm0, __shfl_xor_sync(0xffffffffu, rm0, 2));
        rm1 = fmaxf(rm1, __shfl_xor_sync(0xffffffffu, rm1, 1));
        rm1 = fmaxf(rm1, __shfl_xor_sync(0xffffffffu, rm1, 2));

        float mn0 = fmaxf(m0, rm0), mn1 = fmaxf(m1, rm1);
        float f0 = __expf(m0 - mn0), f1 = __expf(m1 - mn1);
        m0 = mn0; m1 = mn1;

        // exp via ex2.approx.f16x2 (2 values per MUFU op); sums in fp32
        const float L2E = 1.44269504088896f;
        float mb0 = mn0 * L2E, mb1 = mn1 * L2E;
        uint32_t P0[8], P1[8];
        float rs0 = 0.f, rs1 = 0.f;
        #pragma unroll
        for (int nt = 0; nt < 8; nt++) {
            float u0 = fmaf(s[nt][0], L2E, -mb0);
            float u1 = fmaf(s[nt][1], L2E, -mb0);
            float u2 = fmaf(s[nt][2], L2E, -mb1);
            float u3 = fmaf(s[nt][3], L2E, -mb1);
            uint32_t h01 = h2pack(u0, u1);
            uint32_t h23 = h2pack(u2, u3);
            asm("ex2.approx.f16x2 %0, %1;" : "=r"(P0[nt]) : "r"(h01));
            asm("ex2.approx.f16x2 %0, %1;" : "=r"(P1[nt]) : "r"(h23));
            __half2 e01 = *(__half2*)&P0[nt];
            __half2 e23 = *(__half2*)&P1[nt];
            rs0 += __low2float(e01) + __high2float(e01);
            rs1 += __low2float(e23) + __high2float(e23);
        }
        l0 = l0*f0 + rs0;
        l1 = l1*f1 + rs1;
        #pragma unroll
        for (int nt = 0; nt < 8; nt++) {
            o[nt][0] *= f0; o[nt][1] *= f0;
            o[nt][2] *= f1; o[nt][3] *= f1;
        }

        // O += P V : P already packed as half2 in P0/P1
        #pragma unroll
        for (int kk = 0; kk < 4; kk++) {
            uint32_t a0 = P0[2*kk  ];
            uint32_t a1 = P1[2*kk  ];
            uint32_t a2 = P0[2*kk+1];
            uint32_t a3 = P1[2*kk+1];
            #pragma unroll
            for (int ntp = 0; ntp < 4; ntp++) {
                uint32_t r0, r1, r2, r3;
                uint32_t va = vbase + ((kk*16 + vRow)*KVW + ntp*8 + vWof)*4;
                LDSM_X4T(r0, r1, r2, r3, va);
                mma16(o[2*ntp  ], a0, a1, a2, a3, r0, r1);
                mma16(o[2*ntp+1], a0, a1, a2, a3, r2, r3);
            }
        }
    }

    l0 += __shfl_xor_sync(0xffffffffu, l0, 1);
    l0 += __shfl_xor_sync(0xffffffffu, l0, 2);
    l1 += __shfl_xor_sync(0xffffffffu, l1, 1);
    l1 += __shfl_xor_sync(0xffffffffu, l1, 2);
    float inv0 = 1.f / l0, inv1 = 1.f / l1;

    int r0 = qt*128 + rw + g, r1 = r0 + 8;
    __half* y0 = g_y + (size_t)(b*SEQ + r0)*CDIM + h*HDIM;
    __half* y1 = g_y + (size_t)(b*SEQ + r1)*CDIM + h*HDIM;
    #pragma unroll
    for (int nt = 0; nt < 8; nt++) {
        int c = nt*8 + tg*2;
        *(uint32_t*)(y0 + c) = h2pack(o[nt][0]*inv0, o[nt][1]*inv0);
        *(uint32_t*)(y1 + c) = h2pack(o[nt][2]*inv1, o[nt][3]*inv1);
    }
}

// ===================== host =================================================
extern "C" void kernel_launch(void* const* d_in, const int* in_sizes, int n_in,
                              void* d_out, int out_size) {
    const float* x      = (const float*)d_in[0];
    const float* mask   = (const float*)d_in[1];
    const float* W_attn = (const float*)d_in[2];
    const float* b_attn = (const float*)d_in[3];
    const float* W_proj = (const float*)d_in[4];
    const float* b_proj = (const float*)d_in[5];
    float* out = (float*)d_out;

    cudaFuncSetAttribute((const void*)flash_attn,
                         cudaFuncAttributeMaxDynamicSharedMemorySize, FLASH_SMEM);
    cudaFuncSetAttribute((const void*)qkv_gemm,
                         cudaFuncAttributeMaxDynamicSharedMemorySize, G_SMEM);
    cudaFuncSetAttribute((const void*)proj_gemm,
                         cudaFuncAttributeMaxDynamicSharedMemorySize, G_SMEM);

    prep_all<<<XB + WAB + WPB, 256>>>(x, W_attn, W_proj);

    dim3 g1(CDIM3/128, MROWS/128);     // 18 x 64
    qkv_gemm<<<g1, 256, G_SMEM>>>(b_attn);

    dim3 g2(SEQ/128, NHEAD*NB);        // 16 x 48 (h-major: mask L2 reuse over b)
    flash_attn<<<g2, 256, FLASH_SMEM>>>(mask);

    dim3 g3(CDIM/128, MROWS/128);      // 6 x 64
    proj_gemm<<<g3, 256, G_SMEM>>>(b_proj, out);
}

// round 16
// speedup vs baseline: 1.0688x; 1.0021x over previous
#include <cuda_runtime.h>
#include <cuda_fp16.h>
#include <cstdint>
#include <cfloat>

#define NHEAD 12
#define NB    4
#define SEQ   2048
#define HDIM  64
#define CDIM  768
#define CDIM3 2304
#define MROWS (NB*SEQ)   // 8192

// fp16 scratch (static device globals: no runtime allocation)
__device__ __align__(16) __half g_q[NB*NHEAD*SEQ*HDIM];  // q pre-scaled by 0.125
__device__ __align__(16) __half g_k[NB*NHEAD*SEQ*HDIM];
__device__ __align__(16) __half g_v[NB*NHEAD*SEQ*HDIM];
__device__ __align__(16) __half g_y[MROWS*CDIM];
__device__ __align__(16) __half g_xh[MROWS*CDIM];        // x fp16
__device__ __align__(16) __half g_wah[CDIM3*CDIM];       // W_attn^T fp16 [n][k]
__device__ __align__(16) __half g_wph[CDIM*CDIM];        // W_proj^T fp16 [n][k]

__device__ __forceinline__ uint32_t h2pack(float lo, float hi) {
    uint32_t u;
    asm("cvt.rn.f16x2.f32 %0, %1, %2;" : "=r"(u) : "f"(hi), "f"(lo));
    return u;
}

__device__ __forceinline__ uint32_t smem_u32(const void* p) {
    uint32_t a;
    asm("{ .reg .u64 t; cvta.to.shared.u64 t, %1; cvt.u32.u64 %0, t; }"
        : "=r"(a) : "l"(p));
    return a;
}

#define CP16A(dst, src) \
    asm volatile("cp.async.ca.shared.global [%0], [%1], 16;" \
                 :: "r"((uint32_t)(dst)), "l"((size_t)(src)) : "memory")
#define CP_COMMIT() asm volatile("cp.async.commit_group;" ::: "memory")
#define CP_WAIT0()  asm volatile("cp.async.wait_group 0;" ::: "memory")

__device__ __forceinline__ void mma16(float* d,
    uint32_t a0, uint32_t a1, uint32_t a2, uint32_t a3,
    uint32_t b0, uint32_t b1) {
    asm volatile(
      "mma.sync.aligned.m16n8k16.row.col.f32.f16.f16.f32 "
      "{%0,%1,%2,%3}, {%4,%5,%6,%7}, {%8,%9}, {%0,%1,%2,%3};\n"
      : "+f"(d[0]), "+f"(d[1]), "+f"(d[2]), "+f"(d[3])
      : "r"(a0), "r"(a1), "r"(a2), "r"(a3), "r"(b0), "r"(b1));
}

#define LDSM_X4(r0,r1,r2,r3,addr) \
    asm volatile("ldmatrix.sync.aligned.m8n8.x4.shared.b16 {%0,%1,%2,%3}, [%4];" \
        : "=r"(r0), "=r"(r1), "=r"(r2), "=r"(r3) : "r"(addr))
#define LDSM_X4T(r0,r1,r2,r3,addr) \
    asm volatile("ldmatrix.sync.aligned.m8n8.x4.trans.shared.b16 {%0,%1,%2,%3}, [%4];" \
        : "=r"(r0), "=r"(r1), "=r"(r2), "=r"(r3) : "r"(addr))

// ===================== merged prep kernel ===================================
#define XB  (MROWS*CDIM/1024)            // 6144
#define WAB ((CDIM3/32)*(CDIM/32))       // 1728
#define WPB ((CDIM/32)*(CDIM/32))        // 576

__global__ __launch_bounds__(256) void prep_all(
    const float* __restrict__ x,
    const float* __restrict__ W_attn,
    const float* __restrict__ W_proj) {
    __shared__ float t[32][33];
    int bx = blockIdx.x;
    if (bx < XB) {
        size_t i = ((size_t)bx * 256 + threadIdx.x) * 4;
        float4 v = *(const float4*)(x + i);
        uint2 o;
        o.x = h2pack(v.x, v.y);
        o.y = h2pack(v.z, v.w);
        *(uint2*)(g_xh + i) = o;
        return;
    }
    const float* src; __half* dst; int K, N, b;
    if (bx < XB + WAB) {
        b = bx - XB; src = W_attn; dst = g_wah; K = CDIM; N = CDIM3;
    } else {
        b = bx - XB - WAB; src = W_proj; dst = g_wph; K = CDIM; N = CDIM;
    }
    int nb = (b % (N/32)) * 32, kb = (b / (N/32)) * 32;
    int tx = threadIdx.x & 31, ty = threadIdx.x >> 5;
    #pragma unroll
    for (int r = 0; r < 4; r++)
        t[ty + r*8][tx] = src[(size_t)(kb + ty + r*8) * N + nb + tx];
    __syncthreads();
    #pragma unroll
    for (int r = 0; r < 4; r++)
        dst[(size_t)(nb + ty + r*8) * K + kb + tx] = __float2half_rn(t[tx][ty + r*8]);
}

// ===================== fp16 GEMM core (128x128x64, cp.async 2-stage) ========
// R12-exact: 2 stages, all .ca, two barriers per K-chunk, no frag buffering.
#define GP 36                 // smem pitch in words (64 halves + 4 pad words)
#define ABS (128*GP)          // words per tile array
#define G_SMEM (2*2*ABS*4)    // 73728 B

#define GEMM_LANE_SETUP() \
    const int tid = threadIdx.x; \
    const int wid = tid >> 5, lane = tid & 31; \
    const int g = lane >> 2, tg = lane & 3; \
    const int wM = wid & 3, wN = wid >> 2; \
    const int aRow = (lane & 7) + ((lane >> 3) & 1) * 8, aWof = (lane >> 4) * 4; \
    const int bRow = (lane & 7) + ((lane >> 4) & 1) * 8, bWof = ((lane >> 3) & 1) * 4; \
    const int lrow = tid >> 3, lseg = tid & 7;

#define GEMM_ISSUE(kb, st) do { \
    size_t ko_ = (size_t)(kb)*64*2; \
    uint32_t ad_ = sb + ((st)*2*ABS)*4; \
    uint32_t bd_ = sb + ((st)*2*ABS + ABS)*4; \
    _Pragma("unroll") \
    for (int j_ = 0; j_ < 4; j_++) { \
        CP16A(ad_ + (((lrow + j_*32)*GP + lseg*4))*4, aG + (size_t)(j_*32)*CDIM*2 + ko_); \
        CP16A(bd_ + (((lrow + j_*32)*GP + lseg*4))*4, bG + (size_t)(j_*32)*CDIM*2 + ko_); \
    } \
    CP_COMMIT(); \
} while (0)

#define GEMM_MAINLOOP() \
    float acc[2][8][4]; \
    _Pragma("unroll") \
    for (int i = 0; i < 2; i++) \
        _Pragma("unroll") \
        for (int j = 0; j < 8; j++) \
            _Pragma("unroll") \
            for (int e = 0; e < 4; e++) acc[i][j][e] = 0.f; \
    GEMM_ISSUE(0, 0); \
    for (int kb = 0; kb < CDIM/64; kb++) { \
        CP_WAIT0(); \
        __syncthreads(); \
        if (kb + 1 < CDIM/64) GEMM_ISSUE(kb + 1, (kb + 1) & 1); \
        const uint32_t sbA = sb + ((kb & 1)*2*ABS)*4; \
        const uint32_t sbB = sbA + ABS*4; \
        _Pragma("unroll") \
        for (int kk = 0; kk < 4; kk++) { \
            uint32_t a0[4], a1[4]; \
            LDSM_X4(a0[0],a0[1],a0[2],a0[3], sbA + ((wM*32      + aRow)*GP + kk*8 + aWof)*4); \
            LDSM_X4(a1[0],a1[1],a1[2],a1[3], sbA + ((wM*32 + 16 + aRow)*GP + kk*8 + aWof)*4); \
            _Pragma("unroll") \
            for (int ntp = 0; ntp < 4; ntp++) { \
                uint32_t b0, b1, b2, b3; \
                LDSM_X4(b0, b1, b2, b3, \
                        sbB + ((wN*64 + ntp*16 + bRow)*GP + kk*8 + bWof)*4); \
                mma16(acc[0][2*ntp  ], a0[0],a0[1],a0[2],a0[3], b0, b1); \
                mma16(acc[0][2*ntp+1], a0[0],a0[1],a0[2],a0[3], b2, b3); \
                mma16(acc[1][2*ntp  ], a1[0],a1[1],a1[2],a1[3], b0, b1); \
                mma16(acc[1][2*ntp+1], a1[0],a1[1],a1[2],a1[3], b2, b3); \
            } \
        } \
        __syncthreads(); \
    }

// ---------------------------------------------------------------------------
// Kernel 1: qkv = xh @ wah^T + b_attn -> fp16 head-major q/k/v (q * 0.125)
// ---------------------------------------------------------------------------
__global__ __launch_bounds__(256) void qkv_gemm(const float* __restrict__ bias) {
    extern __shared__ uint32_t smw[];
    uint32_t sb = smem_u32(smw);
    GEMM_LANE_SETUP();
    const int rowBase = blockIdx.y * 128;
    const int colBase = blockIdx.x * 128;
    const size_t aG = __cvta_generic_to_global(g_xh  + (size_t)(rowBase + lrow)*CDIM + lseg*8);
    const size_t bG = __cvta_generic_to_global(g_wah + (size_t)(colBase + lrow)*CDIM + lseg*8);

    GEMM_MAINLOOP();

    const int which = colBase / CDIM;
    const int cjBase = colBase % CDIM;
    __half* dst = (which == 0) ? g_q : (which == 1 ? g_k : g_v);
    const float qs = (which == 0) ? 0.125f : 1.0f;

    #pragma unroll
    for (int mt = 0; mt < 2; mt++) {
        int r0g = rowBase + wM*32 + mt*16 + g;
        int r1g = r0g + 8;
        int b0i = r0g >> 11, t0 = r0g & 2047;
        int b1i = r1g >> 11, t1 = r1g & 2047;
        #pragma unroll
        for (int nt = 0; nt < 8; nt++) {
            int cj = cjBase + wN*64 + nt*8 + tg*2;
            int h = cj >> 6, d = cj & 63;
            int n = colBase + wN*64 + nt*8 + tg*2;
            float bb0 = bias[n], bb1 = bias[n+1];
            size_t o0 = ((size_t)(b0i*NHEAD + h)*SEQ + t0)*HDIM + d;
            size_t o1 = ((size_t)(b1i*NHEAD + h)*SEQ + t1)*HDIM + d;
            *(uint32_t*)(dst + o0) =
                h2pack((acc[mt][nt][0] + bb0)*qs, (acc[mt][nt][1] + bb1)*qs);
            *(uint32_t*)(dst + o1) =
                h2pack((acc[mt][nt][2] + bb0)*qs, (acc[mt][nt][3] + bb1)*qs);
        }
    }
}

// ---------------------------------------------------------------------------
// Kernel 3: out = y(fp16) @ wph^T + b_proj, fp32 out
// ---------------------------------------------------------------------------
__global__ __launch_bounds__(256) void proj_gemm(const float* __restrict__ bias,
                                                 float* __restrict__ out) {
    extern __shared__ uint32_t smw[];
    uint32_t sb = smem_u32(smw);
    GEMM_LANE_SETUP();
    const int rowBase = blockIdx.y * 128;
    const int colBase = blockIdx.x * 128;
    const size_t aG = __cvta_generic_to_global(g_y   + (size_t)(rowBase + lrow)*CDIM + lseg*8);
    const size_t bG = __cvta_generic_to_global(g_wph + (size_t)(colBase + lrow)*CDIM + lseg*8);

    GEMM_MAINLOOP();

    #pragma unroll
    for (int mt = 0; mt < 2; mt++) {
        int r0g = rowBase + wM*32 + mt*16 + g;
        int r1g = r0g + 8;
        #pragma unroll
        for (int nt = 0; nt < 8; nt++) {
            int n = colBase + wN*64 + nt*8 + tg*2;
            float bb0 = bias[n], bb1 = bias[n+1];
            float2 u0 = {acc[mt][nt][0] + bb0, acc[mt][nt][1] + bb1};
            float2 u1 = {acc[mt][nt][2] + bb0, acc[mt][nt][3] + bb1};
            *(float2*)(out + (size_t)r0g*CDIM + n) = u0;
            *(float2*)(out + (size_t)r1g*CDIM + n) = u1;
        }
    }
}

// ---------------------------------------------------------------------------
// Kernel 2: fp16 flash attention — R12 structure (Br=128, 8 warps, 2 CTAs/SM,
// 2-stage cp.async, f16x2 ex2 softmax, K/V row permutation -> LDG.128 mask).
// Single change vs R12: K/V cp.async uses .ca so sibling CTAs sharing the
// same (b,h) K/V stream on an SM can hit in L1 (lines are single-use per CTA,
// so no self-eviction risk).
// ---------------------------------------------------------------------------
#define KVW 36
#define KV_STAGE (64*KVW)
#define VS_BASE  (2*KV_STAGE)
#define FLASH_SMEM ((4*KV_STAGE)*4)    // 36864 B

__global__ __launch_bounds__(256, 2) void flash_attn(const float* __restrict__ mask) {
    extern __shared__ uint32_t sm[];
    uint32_t sb = smem_u32(sm);

    const int tid = threadIdx.x;
    const int wid = tid >> 5, lane = tid & 31;
    const int g = lane >> 2, tg = lane & 3;
    const int qt = (int)(gridDim.x - 1 - blockIdx.x);
    const int h = blockIdx.y >> 2, b = blockIdx.y & 3;
    const int rw = wid * 16;

    const __half* Qg  = g_q + ((size_t)((b*NHEAD + h)*SEQ) + qt*128)*HDIM;
    const __half* Kg0 = g_k + (size_t)((b*NHEAD + h)*SEQ)*HDIM;
    const __half* Vg0 = g_v + (size_t)((b*NHEAD + h)*SEQ)*HDIM;
    const float*  Mb  = mask + ((size_t)h*SEQ + qt*128)*SEQ;

    // physical smem row = crow; global source row = perm(crow)
    const int crow = tid >> 2, cc0 = tid & 3;
    const int p15 = crow & 15;
    const int l15 = (p15 < 8) ? ((p15 >> 1)*4 + (p15 & 1))
                              : (((p15 - 8) >> 1)*4 + 2 + (p15 & 1));
    const int lsrc = (crow & ~15) | l15;
    const size_t ksrc0 = __cvta_generic_to_global(Kg0 + (size_t)lsrc*HDIM);
    const size_t vsrc0 = __cvta_generic_to_global(Vg0 + (size_t)lsrc*HDIM);
    const uint32_t kdst0 = sb + crow*KVW*4;
    const uint32_t vdst0 = sb + (VS_BASE + crow*KVW)*4;

    #define KV_ISSUE(kt, st) do { \
        size_t ks_ = ksrc0 + (size_t)(kt)*64*HDIM*2; \
        size_t vs_ = vsrc0 + (size_t)(kt)*64*HDIM*2; \
        uint32_t kd_ = kdst0 + (st)*KV_STAGE*4; \
        uint32_t vd_ = vdst0 + (st)*KV_STAGE*4; \
        _Pragma("unroll") \
        for (int j_ = 0; j_ < 2; j_++) { \
            CP16A(kd_ + (cc0 + 4*j_)*16, ks_ + (cc0 + 4*j_)*16); \
            CP16A(vd_ + (cc0 + 4*j_)*16, vs_ + (cc0 + 4*j_)*16); \
        } \
        CP_COMMIT(); \
    } while (0)

    KV_ISSUE(0, 0);

    uint32_t qa[4][4];
    {
        const uint32_t* q0 = (const uint32_t*)(Qg + (size_t)(rw+g)*HDIM);
        const uint32_t* q1 = (const uint32_t*)(Qg + (size_t)(rw+8+g)*HDIM);
        #pragma unroll
        for (int kk = 0; kk < 4; kk++) {
            qa[kk][0] = q0[kk*8 + tg];
            qa[kk][1] = q1[kk*8 + tg];
            qa[kk][2] = q0[kk*8 + tg + 4];
            qa[kk][3] = q1[kk*8 + tg + 4];
        }
    }

    const int kRow = (lane & 7) + ((lane >> 4) & 1) * 8;
    const int kWof = ((lane >> 3) & 1) * 4;
    const int vRow = (lane & 7) + ((lane >> 3) & 1) * 8;
    const int vWof = (lane >> 4) * 4;

    float o[8][4];
    #pragma unroll
    for (int nt = 0; nt < 8; nt++)
        #pragma unroll
        for (int e = 0; e < 4; e++) o[nt][e] = 0.f;
    float m0 = -FLT_MAX, m1 = -FLT_MAX, l0 = 0.f, l1 = 0.f;

    const int ktEnd = 2*qt + 1;
    for (int kt = 0; kt <= ktEnd; kt++) {
        // mask -> S accumulators via LDG.128 (issued before the K/V wait)
        float s[8][4];
        const float* M0 = Mb + (size_t)(rw+g)*SEQ + kt*64;
        const float* M1 = M0 + (size_t)8*SEQ;
        #pragma unroll
        for (int ntp = 0; ntp < 4; ntp++) {
            float4 u = *(const float4*)(M0 + ntp*16 + tg*4);
            float4 w = *(const float4*)(M1 + ntp*16 + tg*4);
            s[2*ntp  ][0] = u.x; s[2*ntp  ][1] = u.y;
            s[2*ntp+1][0] = u.z; s[2*ntp+1][1] = u.w;
            s[2*ntp  ][2] = w.x; s[2*ntp  ][3] = w.y;
            s[2*ntp+1][2] = w.z; s[2*ntp+1][3] = w.w;
        }

        CP_WAIT0();
        __syncthreads();
        if (kt < ktEnd) KV_ISSUE(kt + 1, (kt + 1) & 1);

        const uint32_t kbase = sb + ((kt & 1)*KV_STAGE)*4;
        const uint32_t vbase = sb + (VS_BASE + (kt & 1)*KV_STAGE)*4;

        #pragma unroll
        for (int ntp = 0; ntp < 4; ntp++) {
            #pragma unroll
            for (int kk = 0; kk < 4; kk++) {
                uint32_t r0, r1, r2, r3;
                uint32_t ka = kbase + ((ntp*16 + kRow)*KVW + kk*8 + kWof)*4;
                LDSM_X4(r0, r1, r2, r3, ka);
                mma16(s[2*ntp  ], qa[kk][0],qa[kk][1],qa[kk][2],qa[kk][3], r0, r1);
                mma16(s[2*ntp+1], qa[kk][0],qa[kk][1],qa[kk][2],qa[kk][3], r2, r3);
            }
        }

        float rm0 = -FLT_MAX, rm1 = -FLT_MAX;
        #pragma unroll
        for (int nt = 0; nt < 8; nt++) {
            rm0 = fmaxf(rm0, fmaxf(s[nt][0], s[nt][1]));
            rm1 = fmaxf(rm1, fmaxf(s[nt][2], s[nt][3]));
        }
        rm0 = fmaxf(rm0, __shfl_xor_sync(0xffffffffu, rm0, 1));
        rm0 = fmaxf(rm0, __shfl_xor_sync(0xffffffffu, rm0, 2));
        rm1 = fmaxf(rm1, __shfl_xor_sync(0xffffffffu, rm1, 1));
        rm1 = fmaxf(rm1, __shfl_xor_sync(0xffffffffu, rm1, 2));

        float mn0 = fmaxf(m0, rm0), mn1 = fmaxf(m1, rm1);
        float f0 = __expf(m0 - mn0), f1 = __expf(m1 - mn1);
        m0 = mn0; m1 = mn1;

        // exp via ex2.approx.f16x2 (2 values per MUFU op); sums in fp32
        const float L2E = 1.44269504088896f;
        float mb0 = mn0 * L2E, mb1 = mn1 * L2E;
        uint32_t P0[8], P1[8];
        float rs0 = 0.f, rs1 = 0.f;
        #pragma unroll
        for (int nt = 0; nt < 8; nt++) {
            float u0 = fmaf(s[nt][0], L2E, -mb0);
            float u1 = fmaf(s[nt][1], L2E, -mb0);
            float u2 = fmaf(s[nt][2], L2E, -mb1);
            float u3 = fmaf(s[nt][3], L2E, -mb1);
            uint32_t h01 = h2pack(u0, u1);
            uint32_t h23 = h2pack(u2, u3);
            asm("ex2.approx.f16x2 %0, %1;" : "=r"(P0[nt]) : "r"(h01));
            asm("ex2.approx.f16x2 %0, %1;" : "=r"(P1[nt]) : "r"(h23));
            __half2 e01 = *(__half2*)&P0[nt];
            __half2 e23 = *(__half2*)&P1[nt];
            rs0 += __low2float(e01) + __high2float(e01);
            rs1 += __low2float(e23) + __high2float(e23);
        }
        l0 = l0*f0 + rs0;
        l1 = l1*f1 + rs1;
        #pragma unroll
        for (int nt = 0; nt < 8; nt++) {
            o[nt][0] *= f0; o[nt][1] *= f0;
            o[nt][2] *= f1; o[nt][3] *= f1;
        }

        // O += P V : P already packed as half2 in P0/P1
        #pragma unroll
        for (int kk = 0; kk < 4; kk++) {
            uint32_t a0 = P0[2*kk  ];
            uint32_t a1 = P1[2*kk  ];
            uint32_t a2 = P0[2*kk+1];
            uint32_t a3 = P1[2*kk+1];
            #pragma unroll
            for (int ntp = 0; ntp < 4; ntp++) {
                uint32_t r0, r1, r2, r3;
                uint32_t va = vbase + ((kk*16 + vRow)*KVW + ntp*8 + vWof)*4;
                LDSM_X4T(r0, r1, r2, r3, va);
                mma16(o[2*ntp  ], a0, a1, a2, a3, r0, r1);
                mma16(o[2*ntp+1], a0, a1, a2, a3, r2, r3);
            }
        }
    }

    l0 += __shfl_xor_sync(0xffffffffu, l0, 1);
    l0 += __shfl_xor_sync(0xffffffffu, l0, 2);
    l1 += __shfl_xor_sync(0xffffffffu, l1, 1);
    l1 += __shfl_xor_sync(0xffffffffu, l1, 2);
    float inv0 = 1.f / l0, inv1 = 1.f / l1;

    int r0 = qt*128 + rw + g, r1 = r0 + 8;
    __half* y0 = g_y + (size_t)(b*SEQ + r0)*CDIM + h*HDIM;
    __half* y1 = g_y + (size_t)(b*SEQ + r1)*CDIM + h*HDIM;
    #pragma unroll
    for (int nt = 0; nt < 8; nt++) {
        int c = nt*8 + tg*2;
        *(uint32_t*)(y0 + c) = h2pack(o[nt][0]*inv0, o[nt][1]*inv0);
        *(uint32_t*)(y1 + c) = h2pack(o[nt][2]*inv1, o[nt][3]*inv1);
    }
}

// ===================== host =================================================
extern "C" void kernel_launch(void* const* d_in, const int* in_sizes, int n_in,
                              void* d_out, int out_size) {
    const float* x      = (const float*)d_in[0];
    const float* mask   = (const float*)d_in[1];
    const float* W_attn = (const float*)d_in[2];
    const float* b_attn = (const float*)d_in[3];
    const float* W_proj = (const float*)d_in[4];
    const float* b_proj = (const float*)d_in[5];
    float* out = (float*)d_out;

    cudaFuncSetAttribute((const void*)flash_attn,
                         cudaFuncAttributeMaxDynamicSharedMemorySize, FLASH_SMEM);
    cudaFuncSetAttribute((const void*)qkv_gemm,
                         cudaFuncAttributeMaxDynamicSharedMemorySize, G_SMEM);
    cudaFuncSetAttribute((const void*)proj_gemm,
                         cudaFuncAttributeMaxDynamicSharedMemorySize, G_SMEM);

    prep_all<<<XB + WAB + WPB, 256>>>(x, W_attn, W_proj);

    dim3 g1(CDIM3/128, MROWS/128);     // 18 x 64
    qkv_gemm<<<g1, 256, G_SMEM>>>(b_attn);

    dim3 g2(SEQ/128, NHEAD*NB);        // 16 x 48 (h-major: mask L2 reuse over b)
    flash_attn<<<g2, 256, FLASH_SMEM>>>(mask);

    dim3 g3(CDIM/128, MROWS/128);      // 6 x 64
    proj_gemm<<<g3, 256, G_SMEM>>>(b_proj, out);
}

// round 17
// speedup vs baseline: 1.0935x; 1.0231x over previous
#include <cuda_runtime.h>
#include <cuda_fp16.h>
#include <cstdint>
#include <cfloat>

#define NHEAD 12
#define NB    4
#define SEQ   2048
#define HDIM  64
#define CDIM  768
#define CDIM3 2304
#define MROWS (NB*SEQ)   // 8192

// fp16 scratch (static device globals: no runtime allocation)
__device__ __align__(16) __half g_q[NB*NHEAD*SEQ*HDIM];  // q pre-scaled by 0.125
__device__ __align__(16) __half g_k[NB*NHEAD*SEQ*HDIM];
__device__ __align__(16) __half g_v[NB*NHEAD*SEQ*HDIM];
__device__ __align__(16) __half g_y[MROWS*CDIM];
__device__ __align__(16) __half g_xh[MROWS*CDIM];        // x fp16
__device__ __align__(16) __half g_wah[CDIM3*CDIM];       // W_attn^T fp16 [n][k]
__device__ __align__(16) __half g_wph[CDIM*CDIM];        // W_proj^T fp16 [n][k]

__device__ __forceinline__ uint32_t h2pack(float lo, float hi) {
    uint32_t u;
    asm("cvt.rn.f16x2.f32 %0, %1, %2;" : "=r"(u) : "f"(hi), "f"(lo));
    return u;
}

__device__ __forceinline__ uint32_t smem_u32(const void* p) {
    uint32_t a;
    asm("{ .reg .u64 t; cvta.to.shared.u64 t, %1; cvt.u32.u64 %0, t; }"
        : "=r"(a) : "l"(p));
    return a;
}

__device__ __forceinline__ void grid_dep_sync() {
#if defined(__CUDA_ARCH__) && (__CUDA_ARCH__ >= 900)
    cudaGridDependencySynchronize();
#endif
}

#define CP16(dst, src) \
    asm volatile("cp.async.cg.shared.global [%0], [%1], 16;" \
                 :: "r"((uint32_t)(dst)), "l"((size_t)(src)) : "memory")
#define CP16A(dst, src) \
    asm volatile("cp.async.ca.shared.global [%0], [%1], 16;" \
                 :: "r"((uint32_t)(dst)), "l"((size_t)(src)) : "memory")
#define CP_COMMIT() asm volatile("cp.async.commit_group;" ::: "memory")
#define CP_WAIT0()  asm volatile("cp.async.wait_group 0;" ::: "memory")

__device__ __forceinline__ void mma16(float* d,
    uint32_t a0, uint32_t a1, uint32_t a2, uint32_t a3,
    uint32_t b0, uint32_t b1) {
    asm volatile(
      "mma.sync.aligned.m16n8k16.row.col.f32.f16.f16.f32 "
      "{%0,%1,%2,%3}, {%4,%5,%6,%7}, {%8,%9}, {%0,%1,%2,%3};\n"
      : "+f"(d[0]), "+f"(d[1]), "+f"(d[2]), "+f"(d[3])
      : "r"(a0), "r"(a1), "r"(a2), "r"(a3), "r"(b0), "r"(b1));
}

#define LDSM_X4(r0,r1,r2,r3,addr) \
    asm volatile("ldmatrix.sync.aligned.m8n8.x4.shared.b16 {%0,%1,%2,%3}, [%4];" \
        : "=r"(r0), "=r"(r1), "=r"(r2), "=r"(r3) : "r"(addr))
#define LDSM_X4T(r0,r1,r2,r3,addr) \
    asm volatile("ldmatrix.sync.aligned.m8n8.x4.trans.shared.b16 {%0,%1,%2,%3}, [%4];" \
        : "=r"(r0), "=r"(r1), "=r"(r2), "=r"(r3) : "r"(addr))

// ===================== merged prep kernel ===================================
#define XB  (MROWS*CDIM/1024)            // 6144
#define WAB ((CDIM3/32)*(CDIM/32))       // 1728
#define WPB ((CDIM/32)*(CDIM/32))        // 576

__global__ __launch_bounds__(256) void prep_all(
    const float* __restrict__ x,
    const float* __restrict__ W_attn,
    const float* __restrict__ W_proj) {
    __shared__ float t[32][33];
    int bx = blockIdx.x;
    if (bx < XB) {
        size_t i = ((size_t)bx * 256 + threadIdx.x) * 4;
        float4 v = *(const float4*)(x + i);
        uint2 o;
        o.x = h2pack(v.x, v.y);
        o.y = h2pack(v.z, v.w);
        *(uint2*)(g_xh + i) = o;
        return;
    }
    const float* src; __half* dst; int K, N, b;
    if (bx < XB + WAB) {
        b = bx - XB; src = W_attn; dst = g_wah; K = CDIM; N = CDIM3;
    } else {
        b = bx - XB - WAB; src = W_proj; dst = g_wph; K = CDIM; N = CDIM;
    }
    int nb = (b % (N/32)) * 32, kb = (b / (N/32)) * 32;
    int tx = threadIdx.x & 31, ty = threadIdx.x >> 5;
    #pragma unroll
    for (int r = 0; r < 4; r++)
        t[ty + r*8][tx] = src[(size_t)(kb + ty + r*8) * N + nb + tx];
    __syncthreads();
    #pragma unroll
    for (int r = 0; r < 4; r++)
        dst[(size_t)(nb + ty + r*8) * K + kb + tx] = __float2half_rn(t[tx][ty + r*8]);
}

// ===================== fp16 GEMM core (128x128x64, cp.async 2-stage) ========
// R12-exact: 2 stages, all .ca, two barriers per K-chunk, no frag buffering.
#define GP 36                 // smem pitch in words (64 halves + 4 pad words)
#define ABS (128*GP)          // words per tile array
#define G_SMEM (2*2*ABS*4)    // 73728 B

#define GEMM_LANE_SETUP() \
    const int tid = threadIdx.x; \
    const int wid = tid >> 5, lane = tid & 31; \
    const int g = lane >> 2, tg = lane & 3; \
    const int wM = wid & 3, wN = wid >> 2; \
    const int aRow = (lane & 7) + ((lane >> 3) & 1) * 8, aWof = (lane >> 4) * 4; \
    const int bRow = (lane & 7) + ((lane >> 4) & 1) * 8, bWof = ((lane >> 3) & 1) * 4; \
    const int lrow = tid >> 3, lseg = tid & 7;

#define GEMM_ISSUE(kb, st) do { \
    size_t ko_ = (size_t)(kb)*64*2; \
    uint32_t ad_ = sb + ((st)*2*ABS)*4; \
    uint32_t bd_ = sb + ((st)*2*ABS + ABS)*4; \
    _Pragma("unroll") \
    for (int j_ = 0; j_ < 4; j_++) { \
        CP16A(ad_ + (((lrow + j_*32)*GP + lseg*4))*4, aG + (size_t)(j_*32)*CDIM*2 + ko_); \
        CP16A(bd_ + (((lrow + j_*32)*GP + lseg*4))*4, bG + (size_t)(j_*32)*CDIM*2 + ko_); \
    } \
    CP_COMMIT(); \
} while (0)

#define GEMM_MAINLOOP() \
    float acc[2][8][4]; \
    _Pragma("unroll") \
    for (int i = 0; i < 2; i++) \
        _Pragma("unroll") \
        for (int j = 0; j < 8; j++) \
            _Pragma("unroll") \
            for (int e = 0; e < 4; e++) acc[i][j][e] = 0.f; \
    GEMM_ISSUE(0, 0); \
    for (int kb = 0; kb < CDIM/64; kb++) { \
        CP_WAIT0(); \
        __syncthreads(); \
        if (kb + 1 < CDIM/64) GEMM_ISSUE(kb + 1, (kb + 1) & 1); \
        const uint32_t sbA = sb + ((kb & 1)*2*ABS)*4; \
        const uint32_t sbB = sbA + ABS*4; \
        _Pragma("unroll") \
        for (int kk = 0; kk < 4; kk++) { \
            uint32_t a0[4], a1[4]; \
            LDSM_X4(a0[0],a0[1],a0[2],a0[3], sbA + ((wM*32      + aRow)*GP + kk*8 + aWof)*4); \
            LDSM_X4(a1[0],a1[1],a1[2],a1[3], sbA + ((wM*32 + 16 + aRow)*GP + kk*8 + aWof)*4); \
            _Pragma("unroll") \
            for (int ntp = 0; ntp < 4; ntp++) { \
                uint32_t b0, b1, b2, b3; \
                LDSM_X4(b0, b1, b2, b3, \
                        sbB + ((wN*64 + ntp*16 + bRow)*GP + kk*8 + bWof)*4); \
                mma16(acc[0][2*ntp  ], a0[0],a0[1],a0[2],a0[3], b0, b1); \
                mma16(acc[0][2*ntp+1], a0[0],a0[1],a0[2],a0[3], b2, b3); \
                mma16(acc[1][2*ntp  ], a1[0],a1[1],a1[2],a1[3], b0, b1); \
                mma16(acc[1][2*ntp+1], a1[0],a1[1],a1[2],a1[3], b2, b3); \
            } \
        } \
        __syncthreads(); \
    }

// ---------------------------------------------------------------------------
// Kernel 1: qkv = xh @ wah^T + b_attn -> fp16 head-major q/k/v (q * 0.125)
// ---------------------------------------------------------------------------
__global__ __launch_bounds__(256) void qkv_gemm(const float* __restrict__ bias) {
    grid_dep_sync();                      // PDL: wait for prep_all outputs
    extern __shared__ uint32_t smw[];
    uint32_t sb = smem_u32(smw);
    GEMM_LANE_SETUP();
    const int rowBase = blockIdx.y * 128;
    const int colBase = blockIdx.x * 128;
    const size_t aG = __cvta_generic_to_global(g_xh  + (size_t)(rowBase + lrow)*CDIM + lseg*8);
    const size_t bG = __cvta_generic_to_global(g_wah + (size_t)(colBase + lrow)*CDIM + lseg*8);

    GEMM_MAINLOOP();

    const int which = colBase / CDIM;
    const int cjBase = colBase % CDIM;
    __half* dst = (which == 0) ? g_q : (which == 1 ? g_k : g_v);
    const float qs = (which == 0) ? 0.125f : 1.0f;

    #pragma unroll
    for (int mt = 0; mt < 2; mt++) {
        int r0g = rowBase + wM*32 + mt*16 + g;
        int r1g = r0g + 8;
        int b0i = r0g >> 11, t0 = r0g & 2047;
        int b1i = r1g >> 11, t1 = r1g & 2047;
        #pragma unroll
        for (int nt = 0; nt < 8; nt++) {
            int cj = cjBase + wN*64 + nt*8 + tg*2;
            int h = cj >> 6, d = cj & 63;
            int n = colBase + wN*64 + nt*8 + tg*2;
            float bb0 = bias[n], bb1 = bias[n+1];
            size_t o0 = ((size_t)(b0i*NHEAD + h)*SEQ + t0)*HDIM + d;
            size_t o1 = ((size_t)(b1i*NHEAD + h)*SEQ + t1)*HDIM + d;
            *(uint32_t*)(dst + o0) =
                h2pack((acc[mt][nt][0] + bb0)*qs, (acc[mt][nt][1] + bb1)*qs);
            *(uint32_t*)(dst + o1) =
                h2pack((acc[mt][nt][2] + bb0)*qs, (acc[mt][nt][3] + bb1)*qs);
        }
    }
}

// ---------------------------------------------------------------------------
// Kernel 3: out = y(fp16) @ wph^T + b_proj, fp32 out
// ---------------------------------------------------------------------------
__global__ __launch_bounds__(256) void proj_gemm(const float* __restrict__ bias,
                                                 float* __restrict__ out) {
    grid_dep_sync();                      // PDL: wait for flash_attn outputs
    extern __shared__ uint32_t smw[];
    uint32_t sb = smem_u32(smw);
    GEMM_LANE_SETUP();
    const int rowBase = blockIdx.y * 128;
    const int colBase = blockIdx.x * 128;
    const size_t aG = __cvta_generic_to_global(g_y   + (size_t)(rowBase + lrow)*CDIM + lseg*8);
    const size_t bG = __cvta_generic_to_global(g_wph + (size_t)(colBase + lrow)*CDIM + lseg*8);

    GEMM_MAINLOOP();

    #pragma unroll
    for (int mt = 0; mt < 2; mt++) {
        int r0g = rowBase + wM*32 + mt*16 + g;
        int r1g = r0g + 8;
        #pragma unroll
        for (int nt = 0; nt < 8; nt++) {
            int n = colBase + wN*64 + nt*8 + tg*2;
            float bb0 = bias[n], bb1 = bias[n+1];
            float2 u0 = {acc[mt][nt][0] + bb0, acc[mt][nt][1] + bb1};
            float2 u1 = {acc[mt][nt][2] + bb0, acc[mt][nt][3] + bb1};
            *(float2*)(out + (size_t)r0g*CDIM + n) = u0;
            *(float2*)(out + (size_t)r1g*CDIM + n) = u1;
        }
    }
}

// ---------------------------------------------------------------------------
// Kernel 2: fp16 flash attention — R12-exact (Br=128, 8 warps, 2 CTAs/SM,
// 2-stage .cg cp.async, f16x2 ex2 softmax, K/V row permutation -> LDG.128).
// ---------------------------------------------------------------------------
#define KVW 36
#define KV_STAGE (64*KVW)
#define VS_BASE  (2*KV_STAGE)
#define FLASH_SMEM ((4*KV_STAGE)*4)    // 36864 B

__global__ __launch_bounds__(256, 2) void flash_attn(const float* __restrict__ mask) {
    grid_dep_sync();                      // PDL: wait for qkv_gemm outputs
    extern __shared__ uint32_t sm[];
    uint32_t sb = smem_u32(sm);

    const int tid = threadIdx.x;
    const int wid = tid >> 5, lane = tid & 31;
    const int g = lane >> 2, tg = lane & 3;
    const int qt = (int)(gridDim.x - 1 - blockIdx.x);
    const int h = blockIdx.y >> 2, b = blockIdx.y & 3;
    const int rw = wid * 16;

    const __half* Qg  = g_q + ((size_t)((b*NHEAD + h)*SEQ) + qt*128)*HDIM;
    const __half* Kg0 = g_k + (size_t)((b*NHEAD + h)*SEQ)*HDIM;
    const __half* Vg0 = g_v + (size_t)((b*NHEAD + h)*SEQ)*HDIM;
    const float*  Mb  = mask + ((size_t)h*SEQ + qt*128)*SEQ;

    // physical smem row = crow; global source row = perm(crow)
    const int crow = tid >> 2, cc0 = tid & 3;
    const int p15 = crow & 15;
    const int l15 = (p15 < 8) ? ((p15 >> 1)*4 + (p15 & 1))
                              : (((p15 - 8) >> 1)*4 + 2 + (p15 & 1));
    const int lsrc = (crow & ~15) | l15;
    const size_t ksrc0 = __cvta_generic_to_global(Kg0 + (size_t)lsrc*HDIM);
    const size_t vsrc0 = __cvta_generic_to_global(Vg0 + (size_t)lsrc*HDIM);
    const uint32_t kdst0 = sb + crow*KVW*4;
    const uint32_t vdst0 = sb + (VS_BASE + crow*KVW)*4;

    #define KV_ISSUE(kt, st) do { \
        size_t ks_ = ksrc0 + (size_t)(kt)*64*HDIM*2; \
        size_t vs_ = vsrc0 + (size_t)(kt)*64*HDIM*2; \
        uint32_t kd_ = kdst0 + (st)*KV_STAGE*4; \
        uint32_t vd_ = vdst0 + (st)*KV_STAGE*4; \
        _Pragma("unroll") \
        for (int j_ = 0; j_ < 2; j_++) { \
            CP16(kd_ + (cc0 + 4*j_)*16, ks_ + (cc0 + 4*j_)*16); \
            CP16(vd_ + (cc0 + 4*j_)*16, vs_ + (cc0 + 4*j_)*16); \
        } \
        CP_COMMIT(); \
    } while (0)

    KV_ISSUE(0, 0);

    uint32_t qa[4][4];
    {
        const uint32_t* q0 = (const uint32_t*)(Qg + (size_t)(rw+g)*HDIM);
        const uint32_t* q1 = (const uint32_t*)(Qg + (size_t)(rw+8+g)*HDIM);
        #pragma unroll
        for (int kk = 0; kk < 4; kk++) {
            qa[kk][0] = q0[kk*8 + tg];
            qa[kk][1] = q1[kk*8 + tg];
            qa[kk][2] = q0[kk*8 + tg + 4];
            qa[kk][3] = q1[kk*8 + tg + 4];
        }
    }

    const int kRow = (lane & 7) + ((lane >> 4) & 1) * 8;
    const int kWof = ((lane >> 3) & 1) * 4;
    const int vRow = (lane & 7) + ((lane >> 3) & 1) * 8;
    const int vWof = (lane >> 4) * 4;

    float o[8][4];
    #pragma unroll
    for (int nt = 0; nt < 8; nt++)
        #pragma unroll
        for (int e = 0; e < 4; e++) o[nt][e] = 0.f;
    float m0 = -FLT_MAX, m1 = -FLT_MAX, l0 = 0.f, l1 = 0.f;

    const int ktEnd = 2*qt + 1;
    for (int kt = 0; kt <= ktEnd; kt++) {
        // mask -> S accumulators via LDG.128 (issued before the K/V wait)
        float s[8][4];
        const float* M0 = Mb + (size_t)(rw+g)*SEQ + kt*64;
        const float* M1 = M0 + (size_t)8*SEQ;
        #pragma unroll
        for (int ntp = 0; ntp < 4; ntp++) {
            float4 u = *(const float4*)(M0 + ntp*16 + tg*4);
            float4 w = *(const float4*)(M1 + ntp*16 + tg*4);
            s[2*ntp  ][0] = u.x; s[2*ntp  ][1] = u.y;
            s[2*ntp+1][0] = u.z; s[2*ntp+1][1] = u.w;
            s[2*ntp  ][2] = w.x; s[2*ntp  ][3] = w.y;
            s[2*ntp+1][2] = w.z; s[2*ntp+1][3] = w.w;
        }

        CP_WAIT0();
        __syncthreads();
        if (kt < ktEnd) KV_ISSUE(kt + 1, (kt + 1) & 1);

        const uint32_t kbase = sb + ((kt & 1)*KV_STAGE)*4;
        const uint32_t vbase = sb + (VS_BASE + (kt & 1)*KV_STAGE)*4;

        #pragma unroll
        for (int ntp = 0; ntp < 4; ntp++) {
            #pragma unroll
            for (int kk = 0; kk < 4; kk++) {
                uint32_t r0, r1, r2, r3;
                uint32_t ka = kbase + ((ntp*16 + kRow)*KVW + kk*8 + kWof)*4;
                LDSM_X4(r0, r1, r2, r3, ka);
                mma16(s[2*ntp  ], qa[kk][0],qa[kk][1],qa[kk][2],qa[kk][3], r0, r1);
                mma16(s[2*ntp+1], qa[kk][0],qa[kk][1],qa[kk][2],qa[kk][3], r2, r3);
            }
        }

        float rm0 = -FLT_MAX, rm1 = -FLT_MAX;
        #pragma unroll
        for (int nt = 0; nt < 8; nt++) {
            rm0 = fmaxf(rm0, fmaxf(s[nt][0], s[nt][1]));
            rm1 = fmaxf(rm1, fmaxf(s[nt][2], s[nt][3]));
        }
        rm0 = fmaxf(rm0, __shfl_xor_sync(0xffffffffu, rm0, 1));
        rm0 = fmaxf(rm0, __shfl_xor_sync(0xffffffffu, rm0, 2));
        rm1 = fmaxf(rm1, __shfl_xor_sync(0xffffffffu, rm1, 1));
        rm1 = fmaxf(rm1, __shfl_xor_sync(0xffffffffu, rm1, 2));

        float mn0 = fmaxf(m0, rm0), mn1 = fmaxf(m1, rm1);
        float f0 = __expf(m0 - mn0), f1 = __expf(m1 - mn1);
        m0 = mn0; m1 = mn1;

        // exp via ex2.approx.f16x2 (2 values per MUFU op); sums in fp32
        const float L2E = 1.44269504088896f;
        float mb0 = mn0 * L2E, mb1 = mn1 * L2E;
        uint32_t P0[8], P1[8];
        float rs0 = 0.f, rs1 = 0.f;
        #pragma unroll
        for (int nt = 0; nt < 8; nt++) {
            float u0 = fmaf(s[nt][0], L2E, -mb0);
            float u1 = fmaf(s[nt][1], L2E, -mb0);
            float u2 = fmaf(s[nt][2], L2E, -mb1);
            float u3 = fmaf(s[nt][3], L2E, -mb1);
            uint32_t h01 = h2pack(u0, u1);
            uint32_t h23 = h2pack(u2, u3);
            asm("ex2.approx.f16x2 %0, %1;" : "=r"(P0[nt]) : "r"(h01));
            asm("ex2.approx.f16x2 %0, %1;" : "=r"(P1[nt]) : "r"(h23));
            __half2 e01 = *(__half2*)&P0[nt];
            __half2 e23 = *(__half2*)&P1[nt];
            rs0 += __low2float(e01) + __high2float(e01);
            rs1 += __low2float(e23) + __high2float(e23);
        }
        l0 = l0*f0 + rs0;
        l1 = l1*f1 + rs1;
        #pragma unroll
        for (int nt = 0; nt < 8; nt++) {
            o[nt][0] *= f0; o[nt][1] *= f0;
            o[nt][2] *= f1; o[nt][3] *= f1;
        }

        // O += P V : P already packed as half2 in P0/P1
        #pragma unroll
        for (int kk = 0; kk < 4; kk++) {
            uint32_t a0 = P0[2*kk  ];
            uint32_t a1 = P1[2*kk  ];
            uint32_t a2 = P0[2*kk+1];
            uint32_t a3 = P1[2*kk+1];
            #pragma unroll
            for (int ntp = 0; ntp < 4; ntp++) {
                uint32_t r0, r1, r2, r3;
                uint32_t va = vbase + ((kk*16 + vRow)*KVW + ntp*8 + vWof)*4;
                LDSM_X4T(r0, r1, r2, r3, va);
                mma16(o[2*ntp  ], a0, a1, a2, a3, r0, r1);
                mma16(o[2*ntp+1], a0, a1, a2, a3, r2, r3);
            }
        }
    }

    l0 += __shfl_xor_sync(0xffffffffu, l0, 1);
    l0 += __shfl_xor_sync(0xffffffffu, l0, 2);
    l1 += __shfl_xor_sync(0xffffffffu, l1, 1);
    l1 += __shfl_xor_sync(0xffffffffu, l1, 2);
    float inv0 = 1.f / l0, inv1 = 1.f / l1;

    int r0 = qt*128 + rw + g, r1 = r0 + 8;
    __half* y0 = g_y + (size_t)(b*SEQ + r0)*CDIM + h*HDIM;
    __half* y1 = g_y + (size_t)(b*SEQ + r1)*CDIM + h*HDIM;
    #pragma unroll
    for (int nt = 0; nt < 8; nt++) {
        int c = nt*8 + tg*2;
        *(uint32_t*)(y0 + c) = h2pack(o[nt][0]*inv0, o[nt][1]*inv0);
        *(uint32_t*)(y1 + c) = h2pack(o[nt][2]*inv1, o[nt][3]*inv1);
    }
}

// ===================== host =================================================
template <typename F, typename... Args>
static inline void launch_pdl(F kernel, dim3 grid, dim3 block, size_t smem,
                              Args... args) {
    cudaLaunchConfig_t cfg = {};
    cfg.gridDim = grid;
    cfg.blockDim = block;
    cfg.dynamicSmemBytes = smem;
    cfg.stream = 0;
    cudaLaunchAttribute at[1];
    at[0].id = cudaLaunchAttributeProgrammaticStreamSerialization;
    at[0].val.programmaticStreamSerializationAllowed = 1;
    cfg.attrs = at;
    cfg.numAttrs = 1;
    cudaLaunchKernelEx(&cfg, kernel, args...);
}

extern "C" void kernel_launch(void* const* d_in, const int* in_sizes, int n_in,
                              void* d_out, int out_size) {
    const float* x      = (const float*)d_in[0];
    const float* mask   = (const float*)d_in[1];
    const float* W_attn = (const float*)d_in[2];
    const float* b_attn = (const float*)d_in[3];
    const float* W_proj = (const float*)d_in[4];
    const float* b_proj = (const float*)d_in[5];
    float* out = (float*)d_out;

    cudaFuncSetAttribute((const void*)flash_attn,
                         cudaFuncAttributeMaxDynamicSharedMemorySize, FLASH_SMEM);
    cudaFuncSetAttribute((const void*)qkv_gemm,
                         cudaFuncAttributeMaxDynamicSharedMemorySize, G_SMEM);
    cudaFuncSetAttribute((const void*)proj_gemm,
                         cudaFuncAttributeMaxDynamicSharedMemorySize, G_SMEM);

    prep_all<<<XB + WAB + WPB, 256>>>(x, W_attn, W_proj);

    // PDL: successors launch into predecessors' drain; each consumer blocks
    // on cudaGridDependencySynchronize() before touching produced data.
    launch_pdl(qkv_gemm, dim3(CDIM3/128, MROWS/128), dim3(256), G_SMEM, b_attn);
    launch_pdl(flash_attn, dim3(SEQ/128, NHEAD*NB), dim3(256), (size_t)FLASH_SMEM, mask);
    launch_pdl(proj_gemm, dim3(CDIM/128, MROWS/128), dim3(256), G_SMEM, b_proj, out);
}